// round 7
// baseline (speedup 1.0000x reference)
#include <cuda_runtime.h>
#include <cuda_bf16.h>
#include <math.h>
#include <stdint.h>

#define SN     16384
#define E_DIM  512
#define C_DIM  1024
#define G_NUM  32
#define CG_NUM 32
#define MAXFIX 8192
#define TAU    2e-4f

// ---------------- scratch (static device globals: no runtime allocation) ----------------
__device__ __align__(16) __nv_bfloat16 g_xh[SN * E_DIM];
__device__ __align__(16) __nv_bfloat16 g_xl[SN * E_DIM];
__device__ __align__(16) __nv_bfloat16 g_x2[SN * E_DIM];
__device__ __align__(16) __nv_bfloat16 g_wh[C_DIM * E_DIM];
__device__ __align__(16) __nv_bfloat16 g_wl[C_DIM * E_DIM];
__device__ __align__(16) __nv_bfloat16 g_w2[C_DIM * E_DIM];
__device__ float g_W2T[C_DIM * E_DIM];   // W2 transposed to (C, E)
__device__ int   g_idx[SN * G_NUM];      // packed argmax indices
__device__ float g_coef[SN * G_NUM * 2]; // straight-through coefficients
__device__ int   g_nfix;
__device__ int   g_fixlist[MAXFIX];

// ---------------- helpers ----------------
static __device__ __forceinline__ uint32_t smem_u32(const void* p) {
    uint32_t a;
    asm("{ .reg .u64 t; cvta.to.shared.u64 t, %1; cvt.u32.u64 %0, t; }" : "=r"(a) : "l"(p));
    return a;
}
static __device__ __forceinline__ void ldsm_x4(uint32_t* r, uint32_t addr) {
    asm volatile("ldmatrix.sync.aligned.m8n8.x4.shared.b16 {%0,%1,%2,%3}, [%4];"
        : "=r"(r[0]), "=r"(r[1]), "=r"(r[2]), "=r"(r[3]) : "r"(addr));
}
static __device__ __forceinline__ void mma_bf16(float* d, const uint32_t* a, const uint32_t* b) {
    asm volatile("mma.sync.aligned.m16n8k16.row.col.f32.bf16.bf16.f32 "
        "{%0,%1,%2,%3}, {%4,%5,%6,%7}, {%8,%9}, {%0,%1,%2,%3};"
        : "+f"(d[0]), "+f"(d[1]), "+f"(d[2]), "+f"(d[3])
        : "r"(a[0]), "r"(a[1]), "r"(a[2]), "r"(a[3]), "r"(b[0]), "r"(b[1]));
}
static __device__ __forceinline__ void cp16(uint32_t dst, const void* src) {
    asm volatile("cp.async.cg.shared.global [%0], [%1], 16;" :: "r"(dst), "l"(src));
}

__global__ void k_reset() { g_nfix = 0; }

// ---------------- split: fp32 -> bf16 triple split ----------------
static __device__ __forceinline__ void split3(float x, __nv_bfloat16& a, __nv_bfloat16& b, __nv_bfloat16& c) {
    a = __float2bfloat16_rn(x);
    float r = x - __bfloat162float(a);
    b = __float2bfloat16_rn(r);
    float r2 = r - __bfloat162float(b);
    c = __float2bfloat16_rn(r2);
}
__global__ void k_split_x(const float* __restrict__ src) {
    size_t i = ((size_t)blockIdx.x * 256 + threadIdx.x) * 4;
    float4 v = *(const float4*)(src + i);
    __nv_bfloat16 h[4], l[4], q[4];
    split3(v.x, h[0], l[0], q[0]); split3(v.y, h[1], l[1], q[1]);
    split3(v.z, h[2], l[2], q[2]); split3(v.w, h[3], l[3], q[3]);
    ((__nv_bfloat162*)(g_xh + i))[0] = __nv_bfloat162(h[0], h[1]);
    ((__nv_bfloat162*)(g_xh + i))[1] = __nv_bfloat162(h[2], h[3]);
    ((__nv_bfloat162*)(g_xl + i))[0] = __nv_bfloat162(l[0], l[1]);
    ((__nv_bfloat162*)(g_xl + i))[1] = __nv_bfloat162(l[2], l[3]);
    ((__nv_bfloat162*)(g_x2 + i))[0] = __nv_bfloat162(q[0], q[1]);
    ((__nv_bfloat162*)(g_x2 + i))[1] = __nv_bfloat162(q[2], q[3]);
}
__global__ void k_split_w(const float* __restrict__ src) {
    size_t i = ((size_t)blockIdx.x * 256 + threadIdx.x) * 4;
    float4 v = *(const float4*)(src + i);
    __nv_bfloat16 h[4], l[4], q[4];
    split3(v.x, h[0], l[0], q[0]); split3(v.y, h[1], l[1], q[1]);
    split3(v.z, h[2], l[2], q[2]); split3(v.w, h[3], l[3], q[3]);
    ((__nv_bfloat162*)(g_wh + i))[0] = __nv_bfloat162(h[0], h[1]);
    ((__nv_bfloat162*)(g_wh + i))[1] = __nv_bfloat162(h[2], h[3]);
    ((__nv_bfloat162*)(g_wl + i))[0] = __nv_bfloat162(l[0], l[1]);
    ((__nv_bfloat162*)(g_wl + i))[1] = __nv_bfloat162(l[2], l[3]);
    ((__nv_bfloat162*)(g_w2 + i))[0] = __nv_bfloat162(q[0], q[1]);
    ((__nv_bfloat162*)(g_w2 + i))[1] = __nv_bfloat162(q[2], q[3]);
}

// ---------------- K0: transpose W2 (E, C) -> g_W2T (C, E) ----------------
__global__ void k_transpose(const float* __restrict__ W2) {
    __shared__ float tile[32][33];
    const int bx = blockIdx.x, by = blockIdx.y;
    const int tx = threadIdx.x, ty = threadIdx.y;
#pragma unroll
    for (int j = 0; j < 4; j++)
        tile[ty + j * 8][tx] = W2[(by * 32 + ty + j * 8) * C_DIM + bx * 32 + tx];
    __syncthreads();
#pragma unroll
    for (int j = 0; j < 4; j++)
        g_W2T[(bx * 32 + ty + j * 8) * E_DIM + by * 32 + tx] = tile[tx][ty + j * 8];
}

// ---------------- K1a: warp-HMMA bf16x3 GEMM + softmax + Gumbel sampling + flagging ----------------
#define BM 128
#define BN 256
#define KC 32
#define NCHUNK (E_DIM / KC)        // 16
#define AROW 80
#define ABUF (128 * AROW)          // 10240
#define BBUF (256 * AROW)          // 20480
#define BUFB (3 * ABUF + 3 * BBUF) // 92160 per stage
#define SM_BIAS (2 * BUFB)         // 184320
#define SM_COF  (SM_BIAS + 1024)
#define SMEM_K1 (SM_COF + 1024)    // 186368
#define LSTR 259

__global__ __launch_bounds__(512, 1)
void k1_mma(const float* __restrict__ b1, const float* __restrict__ coff,
            const float* __restrict__ g1, const float* __restrict__ g2,
            const float* __restrict__ wint, const float* __restrict__ uin,
            float* __restrict__ out_sampled, float* __restrict__ out_soft) {
    extern __shared__ char smem[];
    const uint32_t sb = smem_u32(smem);
    const int tid = threadIdx.x;
    const int lane = tid & 31;
    const int wid = tid >> 5;
    const int wm = wid >> 2, wn = wid & 3;
    const int row0 = blockIdx.y * BM;
    const int col0 = blockIdx.x * BN;
    float* b1s = (float*)(smem + SM_BIAS);
    float* cfs = (float*)(smem + SM_COF);

    if (tid < 256) { b1s[tid] = b1[col0 + tid]; cfs[tid] = coff[col0 + tid]; }

    float acc[2][8][4];
#pragma unroll
    for (int mt = 0; mt < 2; mt++)
#pragma unroll
        for (int nt = 0; nt < 8; nt++)
#pragma unroll
            for (int k = 0; k < 4; k++) acc[mt][nt][k] = 0.0f;

    const __nv_bfloat16* xs[3] = { g_xh, g_xl, g_x2 };
    const __nv_bfloat16* ws[3] = { g_wh, g_wl, g_w2 };

    auto load_chunk = [&](int c, int b) {
        const int kk = c * KC;
#pragma unroll
        for (int p = 0; p < 3; p++) {
            int u = p * 512 + tid;
            int split = u >> 9;
            int rem = u & 511;
            int row = rem >> 2, c16 = rem & 3;
            cp16(sb + b * BUFB + split * ABUF + row * AROW + c16 * 16,
                 xs[split] + (size_t)(row0 + row) * E_DIM + kk + c16 * 8);
        }
#pragma unroll
        for (int p = 0; p < 6; p++) {
            int u = p * 512 + tid;
            int split = u >> 10;
            int rem = u & 1023;
            int row = rem >> 2, c16 = rem & 3;
            cp16(sb + b * BUFB + 3 * ABUF + split * BBUF + row * AROW + c16 * 16,
                 ws[split] + (size_t)(col0 + row) * E_DIM + kk + c16 * 8);
        }
        asm volatile("cp.async.commit_group;" ::: "memory");
    };

    load_chunk(0, 0);
    for (int c = 0; c < NCHUNK; c++) {
        const int b = c & 1;
        if (c + 1 < NCHUNK) {
            load_chunk(c + 1, b ^ 1);
            asm volatile("cp.async.wait_group 1;" ::: "memory");
        } else {
            asm volatile("cp.async.wait_group 0;" ::: "memory");
        }
        __syncthreads();

        const int r = lane & 7, blk = lane >> 3;
        const int am_off = (blk & 1) * 8 + r;
        const int ak_off = (blk >> 1) * 8;
        const int bn_off = (blk >> 1) * 8 + r;
        const int bk_off = (blk & 1) * 8;
#pragma unroll
        for (int kss = 0; kss < 2; kss++) {
            uint32_t afr[3][2][4];
#pragma unroll
            for (int s = 0; s < 3; s++)
#pragma unroll
                for (int mt = 0; mt < 2; mt++)
                    ldsm_x4(afr[s][mt], sb + b * BUFB + s * ABUF
                            + (wm * 32 + mt * 16 + am_off) * AROW + (kss * 16 + ak_off) * 2);
#pragma unroll
            for (int np = 0; np < 4; np++) {
                uint32_t bfr[3][4];
#pragma unroll
                for (int s = 0; s < 3; s++)
                    ldsm_x4(bfr[s], sb + b * BUFB + 3 * ABUF + s * BBUF
                            + (wn * 64 + np * 16 + bn_off) * AROW + (kss * 16 + bk_off) * 2);
#pragma unroll
                for (int mt = 0; mt < 2; mt++)
#pragma unroll
                    for (int nt = 0; nt < 2; nt++) {
                        float* ac = acc[mt][np * 2 + nt];
                        mma_bf16(ac, afr[0][mt], &bfr[0][nt * 2]);   // hh
                        mma_bf16(ac, afr[0][mt], &bfr[1][nt * 2]);   // hl
                        mma_bf16(ac, afr[1][mt], &bfr[0][nt * 2]);   // lh
                        mma_bf16(ac, afr[1][mt], &bfr[1][nt * 2]);   // ll
                        mma_bf16(ac, afr[2][mt], &bfr[0][nt * 2]);   // 2h
                        mma_bf16(ac, afr[0][mt], &bfr[2][nt * 2]);   // h2
                    }
            }
        }
        __syncthreads();
    }

    // -------- logits (reference order) to smem --------
    float* Ls = (float*)smem;
    const int r0l = lane >> 2, c0l = (lane & 3) * 2;
#pragma unroll
    for (int mt = 0; mt < 2; mt++)
#pragma unroll
        for (int nt = 0; nt < 8; nt++) {
            int row = wm * 32 + mt * 16 + r0l;
            int col = wn * 64 + nt * 8 + c0l;
            Ls[row * LSTR + col]           = (acc[mt][nt][0] + b1s[col])     * 3.0f + cfs[col];
            Ls[row * LSTR + col + 1]       = (acc[mt][nt][1] + b1s[col + 1]) * 3.0f + cfs[col + 1];
            Ls[(row + 8) * LSTR + col]     = (acc[mt][nt][2] + b1s[col])     * 3.0f + cfs[col];
            Ls[(row + 8) * LSTR + col + 1] = (acc[mt][nt][3] + b1s[col + 1]) * 3.0f + cfs[col + 1];
        }

    // -------- zero-fill sampled tile (coalesced) --------
    {
        const float4 z = make_float4(0.f, 0.f, 0.f, 0.f);
#pragma unroll
        for (int v = 0; v < 16; v++) {
            int u = v * 512 + tid;
            int row = u >> 6, q = u & 63;
            *(float4*)&out_sampled[(size_t)(row0 + row) * C_DIM + col0 + q * 4] = z;
        }
    }
    __syncthreads();

    // -------- per-(row, group) softmax + Gumbel sampling + gap flagging --------
#pragma unroll 1
    for (int p = 0; p < 2; p++) {
        const int task = p * 512 + tid;
        const int row = task & 127;
        const int gg  = task >> 7;             // 0..7
        const int grow = row0 + row;
        const int gcol = col0 + gg * CG_NUM;
        const int ggrp = gcol >> 5;
        float* Lp = &Ls[row * LSTR + gg * CG_NUM];

        float L[32];
#pragma unroll
        for (int j = 0; j < 32; j++) L[j] = Lp[j];

        float m = -INFINITY;
#pragma unroll
        for (int j = 0; j < 32; j++) m = fmaxf(m, L[j]);
        float e[32];
        float s = 0.0f;
#pragma unroll
        for (int j = 0; j < 32; j++) { e[j] = expf(L[j] - m); s += e[j]; }
        float logs = logf(s);
        float invs = 1.0f / s;

        const float4* G1 = (const float4*)&g1[(size_t)grow * C_DIM + gcol];
        const float4* G2 = (const float4*)&g2[(size_t)grow * C_DIM + gcol];
        int i1 = 0, i2 = 0;
        float bv1 = -INFINITY, bv2 = -INFINITY;
        float bv1b = -INFINITY, bv2b = -INFINITY;
#define UPD1(val, idx) { float v = lp + (val); if (v > bv1) { bv1b = bv1; bv1 = v; i1 = (idx); } else if (v > bv1b) bv1b = v; }
#define UPD2(val, idx) { float u = lp + (val); if (u > bv2) { bv2b = bv2; bv2 = u; i2 = (idx); } else if (u > bv2b) bv2b = u; }
#pragma unroll
        for (int q = 0; q < 8; q++) {
            float4 a = G1[q];
            float4 b = G2[q];
            float lp;
            lp = (L[q * 4 + 0] - m) - logs; UPD1(a.x, q * 4 + 0) UPD2(b.x, q * 4 + 0)
            lp = (L[q * 4 + 1] - m) - logs; UPD1(a.y, q * 4 + 1) UPD2(b.y, q * 4 + 1)
            lp = (L[q * 4 + 2] - m) - logs; UPD1(a.z, q * 4 + 2) UPD2(b.z, q * 4 + 2)
            lp = (L[q * 4 + 3] - m) - logs; UPD1(a.w, q * 4 + 3) UPD2(b.w, q * 4 + 3)
        }
#undef UPD1
#undef UPD2

        float soft_i1 = e[i1] * invs;
        float soft_i2 = e[i2] * invs;

        float uu = uin[grow * G_NUM + ggrp];
        float ww = wint[grow * G_NUM + ggrp];
        float v1 = (uu < 1.0f) ? ww : 1.0f;
        float v2 = (uu < 1.0f) ? (1.0f - ww) : 0.0f;
        float c1, c2;
        if (i1 == i2) { c1 = soft_i1 + ((v1 + v2) - soft_i1); c2 = 0.0f; }
        else          { c1 = soft_i1 + (v1 - soft_i1); c2 = soft_i2 + (v2 - soft_i2); }

        out_sampled[(size_t)grow * C_DIM + gcol + i1] = c1;
        if (i2 != i1) out_sampled[(size_t)grow * C_DIM + gcol + i2] = c2;

#pragma unroll
        for (int j = 0; j < 32; j++) Lp[j] = e[j] * invs;

        int slot = grow * G_NUM + ggrp;
        g_idx[slot] = i1 | (i2 << 8);
        g_coef[2 * slot + 0] = c1;
        g_coef[2 * slot + 1] = c2;

        // flag near-tie groups for exact recompute
        if (fminf(bv1 - bv1b, bv2 - bv2b) < TAU) {
            int fp = atomicAdd(&g_nfix, 1);
            if (fp < MAXFIX) g_fixlist[fp] = slot;
        }
    }
    __syncthreads();

    // -------- cooperative coalesced softmax copy-out --------
#pragma unroll
    for (int v = 0; v < 16; v++) {
        int u = v * 512 + tid;
        int row = u >> 6, q = u & 63;
        float4 sv;
        sv.x = Ls[row * LSTR + q * 4 + 0];
        sv.y = Ls[row * LSTR + q * 4 + 1];
        sv.z = Ls[row * LSTR + q * 4 + 2];
        sv.w = Ls[row * LSTR + q * 4 + 3];
        *(float4*)&out_soft[(size_t)(row0 + row) * C_DIM + col0 + q * 4] = sv;
    }
}

// ---------------- K1b: exact sequential-fp32 recompute of flagged groups ----------------
#define WROWS 513
#define FIXSMEM ((512 + 32 * WROWS + 32) * 4)   // 67840

__global__ __launch_bounds__(256)
void k1b_fix(const float* __restrict__ x, const float* __restrict__ W1,
             const float* __restrict__ b1, const float* __restrict__ coff,
             const float* __restrict__ g1, const float* __restrict__ g2,
             const float* __restrict__ wint, const float* __restrict__ uin,
             float* __restrict__ out_sampled, float* __restrict__ out_soft) {
    extern __shared__ float fs[];
    float* xsh = fs;                  // [512]
    float* wsh = fs + 512;            // [32][513]
    float* sL  = fs + 512 + 32 * WROWS; // [32]

    int n = g_nfix;
    if (n > MAXFIX) n = MAXFIX;
    if ((int)blockIdx.x >= n) return;
    const int slot = g_fixlist[blockIdx.x];
    const int row  = slot >> 5;
    const int ggrp = slot & 31;
    const int gcol = ggrp * 32;
    const int tid = threadIdx.x;

    for (int i = tid; i < 512 / 4; i += 256) {
        float4 v = *(const float4*)&x[(size_t)row * E_DIM + i * 4];
        xsh[i * 4 + 0] = v.x; xsh[i * 4 + 1] = v.y; xsh[i * 4 + 2] = v.z; xsh[i * 4 + 3] = v.w;
    }
    for (int u = tid; u < 32 * 128; u += 256) {
        int j = u >> 7, kq = u & 127;
        float4 v = *(const float4*)&W1[(size_t)(gcol + j) * E_DIM + kq * 4];
        wsh[j * WROWS + kq * 4 + 0] = v.x;
        wsh[j * WROWS + kq * 4 + 1] = v.y;
        wsh[j * WROWS + kq * 4 + 2] = v.z;
        wsh[j * WROWS + kq * 4 + 3] = v.w;
    }
    __syncthreads();

    if (tid < 32) {
        // exact sequential fp32 FMA chain, k = 0..511 (bitwise == the R6 path)
        const float* wr = wsh + tid * WROWS;
        float acc = 0.0f;
        for (int k = 0; k < 512; k++) acc = __fmaf_rn(xsh[k], wr[k], acc);
        sL[tid] = (acc + b1[gcol + tid]) * 3.0f + coff[gcol + tid];
    }
    __syncthreads();

    if (tid == 0) {
        float L[32];
#pragma unroll
        for (int j = 0; j < 32; j++) L[j] = sL[j];
        float m = -INFINITY;
#pragma unroll
        for (int j = 0; j < 32; j++) m = fmaxf(m, L[j]);
        float e[32];
        float s = 0.0f;
#pragma unroll
        for (int j = 0; j < 32; j++) { e[j] = expf(L[j] - m); s += e[j]; }
        float logs = logf(s);
        float invs = 1.0f / s;

        const float* G1 = &g1[(size_t)row * C_DIM + gcol];
        const float* G2 = &g2[(size_t)row * C_DIM + gcol];
        int i1 = 0, i2 = 0;
        float bv1 = -INFINITY, bv2 = -INFINITY;
#pragma unroll
        for (int j = 0; j < 32; j++) {
            float lp = (L[j] - m) - logs;
            float v = lp + G1[j]; if (v > bv1) { bv1 = v; i1 = j; }
            float u = lp + G2[j]; if (u > bv2) { bv2 = u; i2 = j; }
        }

        float soft_i1 = e[i1] * invs;
        float soft_i2 = e[i2] * invs;
        float uu = uin[row * G_NUM + ggrp];
        float ww = wint[row * G_NUM + ggrp];
        float v1 = (uu < 1.0f) ? ww : 1.0f;
        float v2 = (uu < 1.0f) ? (1.0f - ww) : 0.0f;
        float c1, c2;
        if (i1 == i2) { c1 = soft_i1 + ((v1 + v2) - soft_i1); c2 = 0.0f; }
        else          { c1 = soft_i1 + (v1 - soft_i1); c2 = soft_i2 + (v2 - soft_i2); }

#pragma unroll
        for (int j = 0; j < 32; j++) {
            out_soft[(size_t)row * C_DIM + gcol + j] = e[j] * invs;
            out_sampled[(size_t)row * C_DIM + gcol + j] =
                ((j == i1) ? c1 : 0.0f) + ((j == i2 && i2 != i1) ? c2 : 0.0f);
        }
        g_idx[slot] = i1 | (i2 << 8);
        g_coef[2 * slot + 0] = c1;
        g_coef[2 * slot + 1] = c2;
    }
}

// ---------------- K2: sparse projection (SMEM-staged gather) + LayerNorm ----------------
__global__ __launch_bounds__(512)
void k_proj_ln(const float* __restrict__ b2, const float* __restrict__ gamma,
               const float* __restrict__ beta,
               float* __restrict__ out_pos, float* __restrict__ out_neg) {
    extern __shared__ float stage[];  // 64 KB
    const int tid = threadIdx.x;
    const int lane = tid & 31;
    const int wid  = tid >> 5;
    const int rowbase = blockIdx.x * 64;

    float4 h[4][4];
#pragma unroll
    for (int q = 0; q < 4; q++)
#pragma unroll
        for (int k = 0; k < 4; k++) h[q][k] = make_float4(0.f, 0.f, 0.f, 0.f);

    for (int g = 0; g < G_NUM; g++) {
        __syncthreads();
        const float4* src = reinterpret_cast<const float4*>(&g_W2T[g * CG_NUM * E_DIM]);
        float4* dst = reinterpret_cast<float4*>(stage);
#pragma unroll
        for (int p = 0; p < 8; p++) dst[p * 512 + tid] = src[p * 512 + tid];
        __syncthreads();
#pragma unroll
        for (int q = 0; q < 4; q++) {
            int grow = rowbase + wid * 4 + q;
            int slot = grow * G_NUM + g;
            int packed = g_idx[slot];
            int i1 = packed & 255;
            int i2 = (packed >> 8) & 255;
            float c1 = g_coef[2 * slot + 0];
            float c2 = g_coef[2 * slot + 1];
            const float* s1 = &stage[i1 * E_DIM];
            const float* s2 = &stage[i2 * E_DIM];
#pragma unroll
            for (int k = 0; k < 4; k++) {
                float4 a = *reinterpret_cast<const float4*>(&s1[lane * 4 + 128 * k]);
                float4 b = *reinterpret_cast<const float4*>(&s2[lane * 4 + 128 * k]);
                h[q][k].x = fmaf(c1, a.x, fmaf(c2, b.x, h[q][k].x));
                h[q][k].y = fmaf(c1, a.y, fmaf(c2, b.y, h[q][k].y));
                h[q][k].z = fmaf(c1, a.z, fmaf(c2, b.z, h[q][k].z));
                h[q][k].w = fmaf(c1, a.w, fmaf(c2, b.w, h[q][k].w));
            }
        }
    }

    float4 b2r[4], gr[4], br[4];
#pragma unroll
    for (int k = 0; k < 4; k++) {
        b2r[k] = *reinterpret_cast<const float4*>(&b2[lane * 4 + 128 * k]);
        gr[k]  = *reinterpret_cast<const float4*>(&gamma[lane * 4 + 128 * k]);
        br[k]  = *reinterpret_cast<const float4*>(&beta[lane * 4 + 128 * k]);
    }

#pragma unroll
    for (int q = 0; q < 4; q++) {
        int grow = rowbase + wid * 4 + q;
        float sum = 0.0f;
#pragma unroll
        for (int k = 0; k < 4; k++) {
            h[q][k].x += b2r[k].x; h[q][k].y += b2r[k].y;
            h[q][k].z += b2r[k].z; h[q][k].w += b2r[k].w;
            sum += h[q][k].x + h[q][k].y + h[q][k].z + h[q][k].w;
        }
#pragma unroll
        for (int o = 16; o > 0; o >>= 1) sum += __shfl_xor_sync(0xffffffffu, sum, o);
        float mu = sum * (1.0f / 512.0f);
        float vs = 0.0f;
#pragma unroll
        for (int k = 0; k < 4; k++) {
            float dx;
            dx = h[q][k].x - mu; vs += dx * dx;
            dx = h[q][k].y - mu; vs += dx * dx;
            dx = h[q][k].z - mu; vs += dx * dx;
            dx = h[q][k].w - mu; vs += dx * dx;
        }
#pragma unroll
        for (int o = 16; o > 0; o >>= 1) vs += __shfl_xor_sync(0xffffffffu, vs, o);
        float var = vs * (1.0f / 512.0f);
        float sc = rsqrtf(var + 1e-5f);
#pragma unroll
        for (int k = 0; k < 4; k++) {
            float4 o4;
            o4.x = (h[q][k].x - mu) * sc * gr[k].x + br[k].x;
            o4.y = (h[q][k].y - mu) * sc * gr[k].y + br[k].y;
            o4.z = (h[q][k].z - mu) * sc * gr[k].z + br[k].z;
            o4.w = (h[q][k].w - mu) * sc * gr[k].w + br[k].w;
            int off = grow * E_DIM + lane * 4 + 128 * k;
            *reinterpret_cast<float4*>(&out_pos[off]) = o4;
            *reinterpret_cast<float4*>(&out_neg[off]) = o4;
        }
    }
}

extern "C" void kernel_launch(void* const* d_in, const int* in_sizes, int n_in,
                              void* d_out, int out_size) {
    const float* x     = (const float*)d_in[0];
    const float* W1    = (const float*)d_in[1];
    const float* b1    = (const float*)d_in[2];
    const float* coff  = (const float*)d_in[3];
    const float* W2    = (const float*)d_in[4];
    const float* b2    = (const float*)d_in[5];
    const float* gamma = (const float*)d_in[6];
    const float* beta  = (const float*)d_in[7];
    const float* g1    = (const float*)d_in[8];
    const float* g2    = (const float*)d_in[9];
    const float* wi    = (const float*)d_in[10];
    const float* ui    = (const float*)d_in[11];

    float* out = (float*)d_out;
    float* out_sampled = out;
    float* out_soft    = out + (size_t)SN * C_DIM;
    float* out_pos     = out + (size_t)2 * SN * C_DIM;
    float* out_neg     = out_pos + (size_t)SN * E_DIM;

    k_reset<<<1, 1>>>();
    k_split_x<<<SN * E_DIM / 1024, 256>>>(x);
    k_split_w<<<C_DIM * E_DIM / 1024, 256>>>(W1);
    k_transpose<<<dim3(32, 16), dim3(32, 8)>>>(W2);

    cudaFuncSetAttribute(k1_mma, cudaFuncAttributeMaxDynamicSharedMemorySize, SMEM_K1);
    k1_mma<<<dim3(C_DIM / BN, SN / BM), 512, SMEM_K1>>>(
        b1, coff, g1, g2, wi, ui, out_sampled, out_soft);

    cudaFuncSetAttribute(k1b_fix, cudaFuncAttributeMaxDynamicSharedMemorySize, FIXSMEM);
    k1b_fix<<<MAXFIX, 256, FIXSMEM>>>(x, W1, b1, coff, g1, g2, wi, ui,
                                      out_sampled, out_soft);

    cudaFuncSetAttribute(k_proj_ln, cudaFuncAttributeMaxDynamicSharedMemorySize, 65536);
    k_proj_ln<<<SN / 64, 512, 65536>>>(b2, gamma, beta, out_pos, out_neg);
}

// round 10
// speedup vs baseline: 1.2073x; 1.2073x over previous
#include <cuda_runtime.h>
#include <cuda_bf16.h>
#include <math.h>
#include <stdint.h>

#define SN     16384
#define E_DIM  512
#define C_DIM  1024
#define G_NUM  32
#define CG_NUM 32
#define MAXFIX 16384
#define TAU    2e-3f

// ---------------- scratch (static device globals: no runtime allocation) ----------------
__device__ __align__(16) __nv_bfloat16 g_xh[SN * E_DIM];
__device__ __align__(16) __nv_bfloat16 g_xl[SN * E_DIM];
__device__ __align__(16) __nv_bfloat16 g_wh[C_DIM * E_DIM];
__device__ __align__(16) __nv_bfloat16 g_wl[C_DIM * E_DIM];
__device__ float g_W2T[C_DIM * E_DIM];   // W2 transposed to (C, E)
__device__ int   g_idx[SN * G_NUM];      // packed argmax indices
__device__ float g_coef[SN * G_NUM * 2]; // straight-through coefficients
__device__ int   g_nfix;
__device__ int   g_fixlist[MAXFIX];

// ---------------- helpers ----------------
static __device__ __forceinline__ uint32_t smem_u32(const void* p) {
    uint32_t a;
    asm("{ .reg .u64 t; cvta.to.shared.u64 t, %1; cvt.u32.u64 %0, t; }" : "=r"(a) : "l"(p));
    return a;
}
static __device__ __forceinline__ void ldsm_x4(uint32_t* r, uint32_t addr) {
    asm volatile("ldmatrix.sync.aligned.m8n8.x4.shared.b16 {%0,%1,%2,%3}, [%4];"
        : "=r"(r[0]), "=r"(r[1]), "=r"(r[2]), "=r"(r[3]) : "r"(addr));
}
static __device__ __forceinline__ void mma_bf16(float* d, const uint32_t* a, const uint32_t* b) {
    asm volatile("mma.sync.aligned.m16n8k16.row.col.f32.bf16.bf16.f32 "
        "{%0,%1,%2,%3}, {%4,%5,%6,%7}, {%8,%9}, {%0,%1,%2,%3};"
        : "+f"(d[0]), "+f"(d[1]), "+f"(d[2]), "+f"(d[3])
        : "r"(a[0]), "r"(a[1]), "r"(a[2]), "r"(a[3]), "r"(b[0]), "r"(b[1]));
}
static __device__ __forceinline__ void cp16(uint32_t dst, const void* src) {
    asm volatile("cp.async.cg.shared.global [%0], [%1], 16;" :: "r"(dst), "l"(src));
}

__global__ void k_reset() { g_nfix = 0; }

// ---------------- split: fp32 -> bf16 double split ----------------
static __device__ __forceinline__ void split2(float x, __nv_bfloat16& a, __nv_bfloat16& b) {
    a = __float2bfloat16_rn(x);
    b = __float2bfloat16_rn(x - __bfloat162float(a));
}
__global__ void k_split_x(const float* __restrict__ src) {
    size_t i = ((size_t)blockIdx.x * 256 + threadIdx.x) * 4;
    float4 v = *(const float4*)(src + i);
    __nv_bfloat16 h[4], l[4];
    split2(v.x, h[0], l[0]); split2(v.y, h[1], l[1]);
    split2(v.z, h[2], l[2]); split2(v.w, h[3], l[3]);
    ((__nv_bfloat162*)(g_xh + i))[0] = __nv_bfloat162(h[0], h[1]);
    ((__nv_bfloat162*)(g_xh + i))[1] = __nv_bfloat162(h[2], h[3]);
    ((__nv_bfloat162*)(g_xl + i))[0] = __nv_bfloat162(l[0], l[1]);
    ((__nv_bfloat162*)(g_xl + i))[1] = __nv_bfloat162(l[2], l[3]);
}
__global__ void k_split_w(const float* __restrict__ src) {
    size_t i = ((size_t)blockIdx.x * 256 + threadIdx.x) * 4;
    float4 v = *(const float4*)(src + i);
    __nv_bfloat16 h[4], l[4];
    split2(v.x, h[0], l[0]); split2(v.y, h[1], l[1]);
    split2(v.z, h[2], l[2]); split2(v.w, h[3], l[3]);
    ((__nv_bfloat162*)(g_wh + i))[0] = __nv_bfloat162(h[0], h[1]);
    ((__nv_bfloat162*)(g_wh + i))[1] = __nv_bfloat162(h[2], h[3]);
    ((__nv_bfloat162*)(g_wl + i))[0] = __nv_bfloat162(l[0], l[1]);
    ((__nv_bfloat162*)(g_wl + i))[1] = __nv_bfloat162(l[2], l[3]);
}

// ---------------- K0: transpose W2 (E, C) -> g_W2T (C, E) ----------------
__global__ void k_transpose(const float* __restrict__ W2) {
    __shared__ float tile[32][33];
    const int bx = blockIdx.x, by = blockIdx.y;
    const int tx = threadIdx.x, ty = threadIdx.y;
#pragma unroll
    for (int j = 0; j < 4; j++)
        tile[ty + j * 8][tx] = W2[(by * 32 + ty + j * 8) * C_DIM + bx * 32 + tx];
    __syncthreads();
#pragma unroll
    for (int j = 0; j < 4; j++)
        g_W2T[(bx * 32 + ty + j * 8) * E_DIM + by * 32 + tx] = tile[tx][ty + j * 8];
}

// ---------------- K1a: warp-HMMA bf16x2 (3-product) GEMM + sampling + flagging ----------------
#define BM 128
#define BN 256
#define KC 32
#define NCHUNK (E_DIM / KC)        // 16
#define AROW 80
#define ABUF (128 * AROW)          // 10240
#define BBUF (256 * AROW)          // 20480
#define BUFB (2 * ABUF + 2 * BBUF) // 61440 per stage
#define LSTR 259
#define SM_BIAS (BM * LSTR * 4)    // 132608 (beyond stages 122880 and logits union)
#define SM_COF  (SM_BIAS + 1024)
#define SMEM_K1 (SM_COF + 1024)    // 134656

__global__ __launch_bounds__(512, 1)
void k1_mma(const float* __restrict__ b1, const float* __restrict__ coff,
            const float* __restrict__ g1, const float* __restrict__ g2,
            const float* __restrict__ wint, const float* __restrict__ uin,
            float* __restrict__ out_sampled, float* __restrict__ out_soft) {
    extern __shared__ char smem[];
    const uint32_t sb = smem_u32(smem);
    const int tid = threadIdx.x;
    const int lane = tid & 31;
    const int wid = tid >> 5;
    const int wm = wid >> 2, wn = wid & 3;
    const int row0 = blockIdx.y * BM;
    const int col0 = blockIdx.x * BN;
    float* b1s = (float*)(smem + SM_BIAS);
    float* cfs = (float*)(smem + SM_COF);

    if (tid < 256) { b1s[tid] = b1[col0 + tid]; cfs[tid] = coff[col0 + tid]; }

    float acc[2][8][4];
#pragma unroll
    for (int mt = 0; mt < 2; mt++)
#pragma unroll
        for (int nt = 0; nt < 8; nt++)
#pragma unroll
            for (int k = 0; k < 4; k++) acc[mt][nt][k] = 0.0f;

    const __nv_bfloat16* xs[2] = { g_xh, g_xl };
    const __nv_bfloat16* ws[2] = { g_wh, g_wl };

    auto load_chunk = [&](int c, int b) {
        const int kk = c * KC;
#pragma unroll
        for (int p = 0; p < 2; p++) {          // A: 2 splits x 128 rows x 4 x16B
            int u = p * 512 + tid;
            int split = u >> 9;
            int rem = u & 511;
            int row = rem >> 2, c16 = rem & 3;
            cp16(sb + b * BUFB + split * ABUF + row * AROW + c16 * 16,
                 xs[split] + (size_t)(row0 + row) * E_DIM + kk + c16 * 8);
        }
#pragma unroll
        for (int p = 0; p < 4; p++) {          // B: 2 splits x 256 rows x 4 x16B
            int u = p * 512 + tid;
            int split = u >> 10;
            int rem = u & 1023;
            int row = rem >> 2, c16 = rem & 3;
            cp16(sb + b * BUFB + 2 * ABUF + split * BBUF + row * AROW + c16 * 16,
                 ws[split] + (size_t)(col0 + row) * E_DIM + kk + c16 * 8);
        }
        asm volatile("cp.async.commit_group;" ::: "memory");
    };

    load_chunk(0, 0);
    for (int c = 0; c < NCHUNK; c++) {
        const int b = c & 1;
        if (c + 1 < NCHUNK) {
            load_chunk(c + 1, b ^ 1);
            asm volatile("cp.async.wait_group 1;" ::: "memory");
        } else {
            asm volatile("cp.async.wait_group 0;" ::: "memory");
        }
        __syncthreads();

        const int r = lane & 7, blk = lane >> 3;
        const int am_off = (blk & 1) * 8 + r;
        const int ak_off = (blk >> 1) * 8;
        const int bn_off = (blk >> 1) * 8 + r;
        const int bk_off = (blk & 1) * 8;
#pragma unroll
        for (int kss = 0; kss < 2; kss++) {
            uint32_t afr[2][2][4];
#pragma unroll
            for (int s = 0; s < 2; s++)
#pragma unroll
                for (int mt = 0; mt < 2; mt++)
                    ldsm_x4(afr[s][mt], sb + b * BUFB + s * ABUF
                            + (wm * 32 + mt * 16 + am_off) * AROW + (kss * 16 + ak_off) * 2);
#pragma unroll
            for (int np = 0; np < 4; np++) {
                uint32_t bfr[2][4];
#pragma unroll
                for (int s = 0; s < 2; s++)
                    ldsm_x4(bfr[s], sb + b * BUFB + 2 * ABUF + s * BBUF
                            + (wn * 64 + np * 16 + bn_off) * AROW + (kss * 16 + bk_off) * 2);
#pragma unroll
                for (int mt = 0; mt < 2; mt++)
#pragma unroll
                    for (int nt = 0; nt < 2; nt++) {
                        float* ac = acc[mt][np * 2 + nt];
                        mma_bf16(ac, afr[0][mt], &bfr[0][nt * 2]);   // hh
                        mma_bf16(ac, afr[0][mt], &bfr[1][nt * 2]);   // hl
                        mma_bf16(ac, afr[1][mt], &bfr[0][nt * 2]);   // lh
                    }
            }
        }
        __syncthreads();
    }

    // -------- logits (reference order) to smem --------
    float* Ls = (float*)smem;
    const int r0l = lane >> 2, c0l = (lane & 3) * 2;
#pragma unroll
    for (int mt = 0; mt < 2; mt++)
#pragma unroll
        for (int nt = 0; nt < 8; nt++) {
            int row = wm * 32 + mt * 16 + r0l;
            int col = wn * 64 + nt * 8 + c0l;
            Ls[row * LSTR + col]           = (acc[mt][nt][0] + b1s[col])     * 3.0f + cfs[col];
            Ls[row * LSTR + col + 1]       = (acc[mt][nt][1] + b1s[col + 1]) * 3.0f + cfs[col + 1];
            Ls[(row + 8) * LSTR + col]     = (acc[mt][nt][2] + b1s[col])     * 3.0f + cfs[col];
            Ls[(row + 8) * LSTR + col + 1] = (acc[mt][nt][3] + b1s[col + 1]) * 3.0f + cfs[col + 1];
        }

    // -------- zero-fill sampled tile (coalesced) --------
    {
        const float4 z = make_float4(0.f, 0.f, 0.f, 0.f);
#pragma unroll
        for (int v = 0; v < 16; v++) {
            int u = v * 512 + tid;
            int row = u >> 6, q = u & 63;
            *(float4*)&out_sampled[(size_t)(row0 + row) * C_DIM + col0 + q * 4] = z;
        }
    }
    __syncthreads();

    // -------- per-(row, group) softmax + Gumbel sampling + gap flagging --------
#pragma unroll 1
    for (int p = 0; p < 2; p++) {
        const int task = p * 512 + tid;
        const int row = task & 127;
        const int gg  = task >> 7;             // 0..7
        const int grow = row0 + row;
        const int gcol = col0 + gg * CG_NUM;
        const int ggrp = gcol >> 5;
        float* Lp = &Ls[row * LSTR + gg * CG_NUM];

        float L[32];
#pragma unroll
        for (int j = 0; j < 32; j++) L[j] = Lp[j];

        float m = -INFINITY;
#pragma unroll
        for (int j = 0; j < 32; j++) m = fmaxf(m, L[j]);
        float e[32];
        float s = 0.0f;
#pragma unroll
        for (int j = 0; j < 32; j++) { e[j] = expf(L[j] - m); s += e[j]; }
        float logs = logf(s);
        float invs = 1.0f / s;

        const float4* G1 = (const float4*)&g1[(size_t)grow * C_DIM + gcol];
        const float4* G2 = (const float4*)&g2[(size_t)grow * C_DIM + gcol];
        int i1 = 0, i2 = 0;
        float bv1 = -INFINITY, bv2 = -INFINITY;
        float bv1b = -INFINITY, bv2b = -INFINITY;
#define UPD1(val, idx) { float v = lp + (val); if (v > bv1) { bv1b = bv1; bv1 = v; i1 = (idx); } else if (v > bv1b) bv1b = v; }
#define UPD2(val, idx) { float u = lp + (val); if (u > bv2) { bv2b = bv2; bv2 = u; i2 = (idx); } else if (u > bv2b) bv2b = u; }
#pragma unroll
        for (int q = 0; q < 8; q++) {
            float4 a = G1[q];
            float4 b = G2[q];
            float lp;
            lp = (L[q * 4 + 0] - m) - logs; UPD1(a.x, q * 4 + 0) UPD2(b.x, q * 4 + 0)
            lp = (L[q * 4 + 1] - m) - logs; UPD1(a.y, q * 4 + 1) UPD2(b.y, q * 4 + 1)
            lp = (L[q * 4 + 2] - m) - logs; UPD1(a.z, q * 4 + 2) UPD2(b.z, q * 4 + 2)
            lp = (L[q * 4 + 3] - m) - logs; UPD1(a.w, q * 4 + 3) UPD2(b.w, q * 4 + 3)
        }
#undef UPD1
#undef UPD2

        float soft_i1 = e[i1] * invs;
        float soft_i2 = e[i2] * invs;

        float uu = uin[grow * G_NUM + ggrp];
        float ww = wint[grow * G_NUM + ggrp];
        float v1 = (uu < 1.0f) ? ww : 1.0f;
        float v2 = (uu < 1.0f) ? (1.0f - ww) : 0.0f;
        float c1, c2;
        if (i1 == i2) { c1 = soft_i1 + ((v1 + v2) - soft_i1); c2 = 0.0f; }
        else          { c1 = soft_i1 + (v1 - soft_i1); c2 = soft_i2 + (v2 - soft_i2); }

        out_sampled[(size_t)grow * C_DIM + gcol + i1] = c1;
        if (i2 != i1) out_sampled[(size_t)grow * C_DIM + gcol + i2] = c2;

#pragma unroll
        for (int j = 0; j < 32; j++) Lp[j] = e[j] * invs;

        int slot = grow * G_NUM + ggrp;
        g_idx[slot] = i1 | (i2 << 8);
        g_coef[2 * slot + 0] = c1;
        g_coef[2 * slot + 1] = c2;

        // flag near-tie groups for exact sequential-fp32 recompute
        if (fminf(bv1 - bv1b, bv2 - bv2b) < TAU) {
            int fp = atomicAdd(&g_nfix, 1);
            if (fp < MAXFIX) g_fixlist[fp] = slot;
        }
    }
    __syncthreads();

    // -------- cooperative coalesced softmax copy-out --------
#pragma unroll
    for (int v = 0; v < 16; v++) {
        int u = v * 512 + tid;
        int row = u >> 6, q = u & 63;
        float4 sv;
        sv.x = Ls[row * LSTR + q * 4 + 0];
        sv.y = Ls[row * LSTR + q * 4 + 1];
        sv.z = Ls[row * LSTR + q * 4 + 2];
        sv.w = Ls[row * LSTR + q * 4 + 3];
        *(float4*)&out_soft[(size_t)(row0 + row) * C_DIM + col0 + q * 4] = sv;
    }
}

// ---------------- K1b: exact sequential-fp32 recompute of flagged groups ----------------
#define WROWS 513
#define FIXSMEM ((512 + 32 * WROWS + 32) * 4)   // 67840

__global__ __launch_bounds__(256)
void k1b_fix(const float* __restrict__ x, const float* __restrict__ W1,
             const float* __restrict__ b1, const float* __restrict__ coff,
             const float* __restrict__ g1, const float* __restrict__ g2,
             const float* __restrict__ wint, const float* __restrict__ uin,
             float* __restrict__ out_sampled, float* __restrict__ out_soft) {
    extern __shared__ float fs[];
    float* xsh = fs;                    // [512]
    float* wsh = fs + 512;              // [32][513]
    float* sL  = fs + 512 + 32 * WROWS; // [32]

    int n = g_nfix;
    if (n > MAXFIX) n = MAXFIX;
    if ((int)blockIdx.x >= n) return;
    const int slot = g_fixlist[blockIdx.x];
    const int row  = slot >> 5;
    const int ggrp = slot & 31;
    const int gcol = ggrp * 32;
    const int tid = threadIdx.x;

    for (int i = tid; i < 512 / 4; i += 256) {
        float4 v = *(const float4*)&x[(size_t)row * E_DIM + i * 4];
        xsh[i * 4 + 0] = v.x; xsh[i * 4 + 1] = v.y; xsh[i * 4 + 2] = v.z; xsh[i * 4 + 3] = v.w;
    }
    for (int u = tid; u < 32 * 128; u += 256) {
        int j = u >> 7, kq = u & 127;
        float4 v = *(const float4*)&W1[(size_t)(gcol + j) * E_DIM + kq * 4];
        wsh[j * WROWS + kq * 4 + 0] = v.x;
        wsh[j * WROWS + kq * 4 + 1] = v.y;
        wsh[j * WROWS + kq * 4 + 2] = v.z;
        wsh[j * WROWS + kq * 4 + 3] = v.w;
    }
    __syncthreads();

    if (tid < 32) {
        // exact sequential fp32 FMA chain, k = 0..511 (bitwise == the R6 path)
        const float* wr = wsh + tid * WROWS;
        float acc = 0.0f;
        for (int k = 0; k < 512; k++) acc = __fmaf_rn(xsh[k], wr[k], acc);
        sL[tid] = (acc + b1[gcol + tid]) * 3.0f + coff[gcol + tid];
    }
    __syncthreads();

    if (tid == 0) {
        float L[32];
#pragma unroll
        for (int j = 0; j < 32; j++) L[j] = sL[j];
        float m = -INFINITY;
#pragma unroll
        for (int j = 0; j < 32; j++) m = fmaxf(m, L[j]);
        float e[32];
        float s = 0.0f;
#pragma unroll
        for (int j = 0; j < 32; j++) { e[j] = expf(L[j] - m); s += e[j]; }
        float logs = logf(s);
        float invs = 1.0f / s;

        const float* G1 = &g1[(size_t)row * C_DIM + gcol];
        const float* G2 = &g2[(size_t)row * C_DIM + gcol];
        int i1 = 0, i2 = 0;
        float bv1 = -INFINITY, bv2 = -INFINITY;
#pragma unroll
        for (int j = 0; j < 32; j++) {
            float lp = (L[j] - m) - logs;
            float v = lp + G1[j]; if (v > bv1) { bv1 = v; i1 = j; }
            float u = lp + G2[j]; if (u > bv2) { bv2 = u; i2 = j; }
        }

        float soft_i1 = e[i1] * invs;
        float soft_i2 = e[i2] * invs;
        float uu = uin[row * G_NUM + ggrp];
        float ww = wint[row * G_NUM + ggrp];
        float v1 = (uu < 1.0f) ? ww : 1.0f;
        float v2 = (uu < 1.0f) ? (1.0f - ww) : 0.0f;
        float c1, c2;
        if (i1 == i2) { c1 = soft_i1 + ((v1 + v2) - soft_i1); c2 = 0.0f; }
        else          { c1 = soft_i1 + (v1 - soft_i1); c2 = soft_i2 + (v2 - soft_i2); }

#pragma unroll
        for (int j = 0; j < 32; j++) {
            out_soft[(size_t)row * C_DIM + gcol + j] = e[j] * invs;
            out_sampled[(size_t)row * C_DIM + gcol + j] =
                ((j == i1) ? c1 : 0.0f) + ((j == i2 && i2 != i1) ? c2 : 0.0f);
        }
        g_idx[slot] = i1 | (i2 << 8);
        g_coef[2 * slot + 0] = c1;
        g_coef[2 * slot + 1] = c2;
    }
}

// ---------------- K2: sparse projection (SMEM-staged gather) + LayerNorm ----------------
__global__ __launch_bounds__(512)
void k_proj_ln(const float* __restrict__ b2, const float* __restrict__ gamma,
               const float* __restrict__ beta,
               float* __restrict__ out_pos, float* __restrict__ out_neg) {
    extern __shared__ float stage[];  // 64 KB
    const int tid = threadIdx.x;
    const int lane = tid & 31;
    const int wid  = tid >> 5;
    const int rowbase = blockIdx.x * 64;

    float4 h[4][4];
#pragma unroll
    for (int q = 0; q < 4; q++)
#pragma unroll
        for (int k = 0; k < 4; k++) h[q][k] = make_float4(0.f, 0.f, 0.f, 0.f);

    for (int g = 0; g < G_NUM; g++) {
        __syncthreads();
        const float4* src = reinterpret_cast<const float4*>(&g_W2T[g * CG_NUM * E_DIM]);
        float4* dst = reinterpret_cast<float4*>(stage);
#pragma unroll
        for (int p = 0; p < 8; p++) dst[p * 512 + tid] = src[p * 512 + tid];
        __syncthreads();
#pragma unroll
        for (int q = 0; q < 4; q++) {
            int grow = rowbase + wid * 4 + q;
            int slot = grow * G_NUM + g;
            int packed = g_idx[slot];
            int i1 = packed & 255;
            int i2 = (packed >> 8) & 255;
            float c1 = g_coef[2 * slot + 0];
            float c2 = g_coef[2 * slot + 1];
            const float* s1 = &stage[i1 * E_DIM];
            const float* s2 = &stage[i2 * E_DIM];
#pragma unroll
            for (int k = 0; k < 4; k++) {
                float4 a = *reinterpret_cast<const float4*>(&s1[lane * 4 + 128 * k]);
                float4 b = *reinterpret_cast<const float4*>(&s2[lane * 4 + 128 * k]);
                h[q][k].x = fmaf(c1, a.x, fmaf(c2, b.x, h[q][k].x));
                h[q][k].y = fmaf(c1, a.y, fmaf(c2, b.y, h[q][k].y));
                h[q][k].z = fmaf(c1, a.z, fmaf(c2, b.z, h[q][k].z));
                h[q][k].w = fmaf(c1, a.w, fmaf(c2, b.w, h[q][k].w));
            }
        }
    }

    float4 b2r[4], gr[4], br[4];
#pragma unroll
    for (int k = 0; k < 4; k++) {
        b2r[k] = *reinterpret_cast<const float4*>(&b2[lane * 4 + 128 * k]);
        gr[k]  = *reinterpret_cast<const float4*>(&gamma[lane * 4 + 128 * k]);
        br[k]  = *reinterpret_cast<const float4*>(&beta[lane * 4 + 128 * k]);
    }

#pragma unroll
    for (int q = 0; q < 4; q++) {
        int grow = rowbase + wid * 4 + q;
        float sum = 0.0f;
#pragma unroll
        for (int k = 0; k < 4; k++) {
            h[q][k].x += b2r[k].x; h[q][k].y += b2r[k].y;
            h[q][k].z += b2r[k].z; h[q][k].w += b2r[k].w;
            sum += h[q][k].x + h[q][k].y + h[q][k].z + h[q][k].w;
        }
#pragma unroll
        for (int o = 16; o > 0; o >>= 1) sum += __shfl_xor_sync(0xffffffffu, sum, o);
        float mu = sum * (1.0f / 512.0f);
        float vs = 0.0f;
#pragma unroll
        for (int k = 0; k < 4; k++) {
            float dx;
            dx = h[q][k].x - mu; vs += dx * dx;
            dx = h[q][k].y - mu; vs += dx * dx;
            dx = h[q][k].z - mu; vs += dx * dx;
            dx = h[q][k].w - mu; vs += dx * dx;
        }
#pragma unroll
        for (int o = 16; o > 0; o >>= 1) vs += __shfl_xor_sync(0xffffffffu, vs, o);
        float var = vs * (1.0f / 512.0f);
        float sc = rsqrtf(var + 1e-5f);
#pragma unroll
        for (int k = 0; k < 4; k++) {
            float4 o4;
            o4.x = (h[q][k].x - mu) * sc * gr[k].x + br[k].x;
            o4.y = (h[q][k].y - mu) * sc * gr[k].y + br[k].y;
            o4.z = (h[q][k].z - mu) * sc * gr[k].z + br[k].z;
            o4.w = (h[q][k].w - mu) * sc * gr[k].w + br[k].w;
            int off = grow * E_DIM + lane * 4 + 128 * k;
            *reinterpret_cast<float4*>(&out_pos[off]) = o4;
            *reinterpret_cast<float4*>(&out_neg[off]) = o4;
        }
    }
}

extern "C" void kernel_launch(void* const* d_in, const int* in_sizes, int n_in,
                              void* d_out, int out_size) {
    const float* x     = (const float*)d_in[0];
    const float* W1    = (const float*)d_in[1];
    const float* b1    = (const float*)d_in[2];
    const float* coff  = (const float*)d_in[3];
    const float* W2    = (const float*)d_in[4];
    const float* b2    = (const float*)d_in[5];
    const float* gamma = (const float*)d_in[6];
    const float* beta  = (const float*)d_in[7];
    const float* g1    = (const float*)d_in[8];
    const float* g2    = (const float*)d_in[9];
    const float* wi    = (const float*)d_in[10];
    const float* ui    = (const float*)d_in[11];

    float* out = (float*)d_out;
    float* out_sampled = out;
    float* out_soft    = out + (size_t)SN * C_DIM;
    float* out_pos     = out + (size_t)2 * SN * C_DIM;
    float* out_neg     = out_pos + (size_t)SN * E_DIM;

    k_reset<<<1, 1>>>();
    k_split_x<<<SN * E_DIM / 1024, 256>>>(x);
    k_split_w<<<C_DIM * E_DIM / 1024, 256>>>(W1);
    k_transpose<<<dim3(32, 16), dim3(32, 8)>>>(W2);

    cudaFuncSetAttribute(k1_mma, cudaFuncAttributeMaxDynamicSharedMemorySize, SMEM_K1);
    k1_mma<<<dim3(C_DIM / BN, SN / BM), 512, SMEM_K1>>>(
        b1, coff, g1, g2, wi, ui, out_sampled, out_soft);

    cudaFuncSetAttribute(k1b_fix, cudaFuncAttributeMaxDynamicSharedMemorySize, FIXSMEM);
    k1b_fix<<<MAXFIX, 256, FIXSMEM>>>(x, W1, b1, coff, g1, g2, wi, ui,
                                      out_sampled, out_soft);

    cudaFuncSetAttribute(k_proj_ln, cudaFuncAttributeMaxDynamicSharedMemorySize, 65536);
    k_proj_ln<<<SN / 64, 512, 65536>>>(b2, gamma, beta, out_pos, out_neg);
}

// round 13
// speedup vs baseline: 1.4748x; 1.2215x over previous
#include <cuda_runtime.h>
#include <cuda_bf16.h>
#include <math.h>
#include <stdint.h>

#define SN     16384
#define E_DIM  512
#define C_DIM  1024
#define G_NUM  32
#define CG_NUM 32
#define MAXFIX 16384
#define TAU    1e-3f

// ---------------- scratch (static device globals: no runtime allocation) ----------------
__device__ __align__(16) __nv_bfloat16 g_xh[SN * E_DIM];
__device__ __align__(16) __nv_bfloat16 g_xl[SN * E_DIM];
__device__ __align__(16) __nv_bfloat16 g_wh[C_DIM * E_DIM];
__device__ __align__(16) __nv_bfloat16 g_wl[C_DIM * E_DIM];
__device__ float g_W2T[C_DIM * E_DIM];   // W2 transposed to (C, E)
__device__ int   g_idx[SN * G_NUM];      // packed argmax indices
__device__ float g_coef[SN * G_NUM * 2]; // straight-through coefficients
__device__ int   g_nfix;
__device__ int   g_fixlist[MAXFIX];

// ---------------- helpers ----------------
static __device__ __forceinline__ uint32_t smem_u32(const void* p) {
    uint32_t a;
    asm("{ .reg .u64 t; cvta.to.shared.u64 t, %1; cvt.u32.u64 %0, t; }" : "=r"(a) : "l"(p));
    return a;
}
static __device__ __forceinline__ void ldsm_x4(uint32_t* r, uint32_t addr) {
    asm volatile("ldmatrix.sync.aligned.m8n8.x4.shared.b16 {%0,%1,%2,%3}, [%4];"
        : "=r"(r[0]), "=r"(r[1]), "=r"(r[2]), "=r"(r[3]) : "r"(addr));
}
static __device__ __forceinline__ void mma_bf16(float* d, const uint32_t* a, const uint32_t* b) {
    asm volatile("mma.sync.aligned.m16n8k16.row.col.f32.bf16.bf16.f32 "
        "{%0,%1,%2,%3}, {%4,%5,%6,%7}, {%8,%9}, {%0,%1,%2,%3};"
        : "+f"(d[0]), "+f"(d[1]), "+f"(d[2]), "+f"(d[3])
        : "r"(a[0]), "r"(a[1]), "r"(a[2]), "r"(a[3]), "r"(b[0]), "r"(b[1]));
}
static __device__ __forceinline__ void cp16(uint32_t dst, const void* src) {
    asm volatile("cp.async.cg.shared.global [%0], [%1], 16;" :: "r"(dst), "l"(src));
}

__global__ void k_reset() { g_nfix = 0; }

// ---------------- split: fp32 -> bf16 double split ----------------
static __device__ __forceinline__ void split2(float x, __nv_bfloat16& a, __nv_bfloat16& b) {
    a = __float2bfloat16_rn(x);
    b = __float2bfloat16_rn(x - __bfloat162float(a));
}
__global__ void k_split_x(const float* __restrict__ src) {
    size_t i = ((size_t)blockIdx.x * 256 + threadIdx.x) * 4;
    float4 v = *(const float4*)(src + i);
    __nv_bfloat16 h[4], l[4];
    split2(v.x, h[0], l[0]); split2(v.y, h[1], l[1]);
    split2(v.z, h[2], l[2]); split2(v.w, h[3], l[3]);
    ((__nv_bfloat162*)(g_xh + i))[0] = __nv_bfloat162(h[0], h[1]);
    ((__nv_bfloat162*)(g_xh + i))[1] = __nv_bfloat162(h[2], h[3]);
    ((__nv_bfloat162*)(g_xl + i))[0] = __nv_bfloat162(l[0], l[1]);
    ((__nv_bfloat162*)(g_xl + i))[1] = __nv_bfloat162(l[2], l[3]);
}
__global__ void k_split_w(const float* __restrict__ src) {
    size_t i = ((size_t)blockIdx.x * 256 + threadIdx.x) * 4;
    float4 v = *(const float4*)(src + i);
    __nv_bfloat16 h[4], l[4];
    split2(v.x, h[0], l[0]); split2(v.y, h[1], l[1]);
    split2(v.z, h[2], l[2]); split2(v.w, h[3], l[3]);
    ((__nv_bfloat162*)(g_wh + i))[0] = __nv_bfloat162(h[0], h[1]);
    ((__nv_bfloat162*)(g_wh + i))[1] = __nv_bfloat162(h[2], h[3]);
    ((__nv_bfloat162*)(g_wl + i))[0] = __nv_bfloat162(l[0], l[1]);
    ((__nv_bfloat162*)(g_wl + i))[1] = __nv_bfloat162(l[2], l[3]);
}

// ---------------- K0: transpose W2 (E, C) -> g_W2T (C, E) ----------------
__global__ void k_transpose(const float* __restrict__ W2) {
    __shared__ float tile[32][33];
    const int bx = blockIdx.x, by = blockIdx.y;
    const int tx = threadIdx.x, ty = threadIdx.y;
#pragma unroll
    for (int j = 0; j < 4; j++)
        tile[ty + j * 8][tx] = W2[(by * 32 + ty + j * 8) * C_DIM + bx * 32 + tx];
    __syncthreads();
#pragma unroll
    for (int j = 0; j < 4; j++)
        g_W2T[(bx * 32 + ty + j * 8) * E_DIM + by * 32 + tx] = tile[tx][ty + j * 8];
}

// ---------------- K1a: warp-HMMA bf16x2 (3-product) GEMM + sampling + flagging ----------------
#define BM 128
#define BN 256
#define KC 32
#define NCHUNK (E_DIM / KC)        // 16
#define AROW 80
#define ABUF (128 * AROW)          // 10240
#define BBUF (256 * AROW)          // 20480
#define BUFB (2 * ABUF + 2 * BBUF) // 61440 per stage
#define LSTR 259
#define SM_BIAS (BM * LSTR * 4)    // 132608 (beyond stages 122880; Ls union)
#define SM_COF  (SM_BIAS + 1024)
#define SM_IDX  (SM_COF + 1024)    // int[128*8] = 4096
#define SM_CF2  (SM_IDX + 4096)    // float[128*8*2] = 8192
#define SMEM_K1 (SM_CF2 + 8192)    // 146944

__global__ __launch_bounds__(512, 1)
void k1_mma(const float* __restrict__ b1, const float* __restrict__ coff,
            const float* __restrict__ g1, const float* __restrict__ g2,
            const float* __restrict__ wint, const float* __restrict__ uin,
            float* __restrict__ out_sampled, float* __restrict__ out_soft) {
    extern __shared__ char smem[];
    const uint32_t sb = smem_u32(smem);
    const int tid = threadIdx.x;
    const int lane = tid & 31;
    const int wid = tid >> 5;
    const int wm = wid >> 2, wn = wid & 3;
    const int row0 = blockIdx.y * BM;
    const int col0 = blockIdx.x * BN;
    float* b1s = (float*)(smem + SM_BIAS);
    float* cfs = (float*)(smem + SM_COF);
    int*   idx_s = (int*)(smem + SM_IDX);
    float* cf2_s = (float*)(smem + SM_CF2);

    if (tid < 256) { b1s[tid] = b1[col0 + tid]; cfs[tid] = coff[col0 + tid]; }

    float acc[2][8][4];
#pragma unroll
    for (int mt = 0; mt < 2; mt++)
#pragma unroll
        for (int nt = 0; nt < 8; nt++)
#pragma unroll
            for (int k = 0; k < 4; k++) acc[mt][nt][k] = 0.0f;

    const __nv_bfloat16* xs[2] = { g_xh, g_xl };
    const __nv_bfloat16* ws[2] = { g_wh, g_wl };

    auto load_chunk = [&](int c, int b) {
        const int kk = c * KC;
#pragma unroll
        for (int p = 0; p < 2; p++) {          // A: 2 splits x 128 rows x 4 x16B
            int u = p * 512 + tid;
            int split = u >> 9;
            int rem = u & 511;
            int row = rem >> 2, c16 = rem & 3;
            cp16(sb + b * BUFB + split * ABUF + row * AROW + c16 * 16,
                 xs[split] + (size_t)(row0 + row) * E_DIM + kk + c16 * 8);
        }
#pragma unroll
        for (int p = 0; p < 4; p++) {          // B: 2 splits x 256 rows x 4 x16B
            int u = p * 512 + tid;
            int split = u >> 10;
            int rem = u & 1023;
            int row = rem >> 2, c16 = rem & 3;
            cp16(sb + b * BUFB + 2 * ABUF + split * BBUF + row * AROW + c16 * 16,
                 ws[split] + (size_t)(col0 + row) * E_DIM + kk + c16 * 8);
        }
        asm volatile("cp.async.commit_group;" ::: "memory");
    };

    load_chunk(0, 0);
    for (int c = 0; c < NCHUNK; c++) {
        const int b = c & 1;
        if (c + 1 < NCHUNK) {
            load_chunk(c + 1, b ^ 1);
            asm volatile("cp.async.wait_group 1;" ::: "memory");
        } else {
            asm volatile("cp.async.wait_group 0;" ::: "memory");
        }
        __syncthreads();

        const int r = lane & 7, blk = lane >> 3;
        const int am_off = (blk & 1) * 8 + r;
        const int ak_off = (blk >> 1) * 8;
        const int bn_off = (blk >> 1) * 8 + r;
        const int bk_off = (blk & 1) * 8;
#pragma unroll
        for (int kss = 0; kss < 2; kss++) {
            uint32_t afr[2][2][4];
#pragma unroll
            for (int s = 0; s < 2; s++)
#pragma unroll
                for (int mt = 0; mt < 2; mt++)
                    ldsm_x4(afr[s][mt], sb + b * BUFB + s * ABUF
                            + (wm * 32 + mt * 16 + am_off) * AROW + (kss * 16 + ak_off) * 2);
#pragma unroll
            for (int np = 0; np < 4; np++) {
                uint32_t bfr[2][4];
#pragma unroll
                for (int s = 0; s < 2; s++)
                    ldsm_x4(bfr[s], sb + b * BUFB + 2 * ABUF + s * BBUF
                            + (wn * 64 + np * 16 + bn_off) * AROW + (kss * 16 + bk_off) * 2);
#pragma unroll
                for (int mt = 0; mt < 2; mt++)
#pragma unroll
                    for (int nt = 0; nt < 2; nt++) {
                        float* ac = acc[mt][np * 2 + nt];
                        mma_bf16(ac, afr[0][mt], &bfr[0][nt * 2]);   // hh
                        mma_bf16(ac, afr[0][mt], &bfr[1][nt * 2]);   // hl
                        mma_bf16(ac, afr[1][mt], &bfr[0][nt * 2]);   // lh
                    }
            }
        }
        __syncthreads();
    }

    // -------- logits (reference order) to smem --------
    float* Ls = (float*)smem;
    const int r0l = lane >> 2, c0l = (lane & 3) * 2;
#pragma unroll
    for (int mt = 0; mt < 2; mt++)
#pragma unroll
        for (int nt = 0; nt < 8; nt++) {
            int row = wm * 32 + mt * 16 + r0l;
            int col = wn * 64 + nt * 8 + c0l;
            Ls[row * LSTR + col]           = (acc[mt][nt][0] + b1s[col])     * 3.0f + cfs[col];
            Ls[row * LSTR + col + 1]       = (acc[mt][nt][1] + b1s[col + 1]) * 3.0f + cfs[col + 1];
            Ls[(row + 8) * LSTR + col]     = (acc[mt][nt][2] + b1s[col])     * 3.0f + cfs[col];
            Ls[(row + 8) * LSTR + col + 1] = (acc[mt][nt][3] + b1s[col + 1]) * 3.0f + cfs[col + 1];
        }
    __syncthreads();

    // -------- per-(row, group) softmax + Gumbel sampling + gap flagging --------
#pragma unroll 1
    for (int p = 0; p < 2; p++) {
        const int task = p * 512 + tid;
        const int row = task & 127;
        const int gg  = task >> 7;             // 0..7
        const int grow = row0 + row;
        const int gcol = col0 + gg * CG_NUM;
        const int ggrp = gcol >> 5;
        float* Lp = &Ls[row * LSTR + gg * CG_NUM];

        float L[32];
#pragma unroll
        for (int j = 0; j < 32; j++) L[j] = Lp[j];

        float m = -INFINITY;
#pragma unroll
        for (int j = 0; j < 32; j++) m = fmaxf(m, L[j]);
        float e[32];
        float s = 0.0f;
#pragma unroll
        for (int j = 0; j < 32; j++) { e[j] = expf(L[j] - m); s += e[j]; }
        float logs = logf(s);
        float invs = 1.0f / s;

        const float4* G1 = (const float4*)&g1[(size_t)grow * C_DIM + gcol];
        const float4* G2 = (const float4*)&g2[(size_t)grow * C_DIM + gcol];
        int i1 = 0, i2 = 0;
        float bv1 = -INFINITY, bv2 = -INFINITY;
        float bv1b = -INFINITY, bv2b = -INFINITY;
#define UPD1(val, idx) { float v = lp + (val); if (v > bv1) { bv1b = bv1; bv1 = v; i1 = (idx); } else if (v > bv1b) bv1b = v; }
#define UPD2(val, idx) { float u = lp + (val); if (u > bv2) { bv2b = bv2; bv2 = u; i2 = (idx); } else if (u > bv2b) bv2b = u; }
#pragma unroll
        for (int q = 0; q < 8; q++) {
            float4 a = G1[q];
            float4 b = G2[q];
            float lp;
            lp = (L[q * 4 + 0] - m) - logs; UPD1(a.x, q * 4 + 0) UPD2(b.x, q * 4 + 0)
            lp = (L[q * 4 + 1] - m) - logs; UPD1(a.y, q * 4 + 1) UPD2(b.y, q * 4 + 1)
            lp = (L[q * 4 + 2] - m) - logs; UPD1(a.z, q * 4 + 2) UPD2(b.z, q * 4 + 2)
            lp = (L[q * 4 + 3] - m) - logs; UPD1(a.w, q * 4 + 3) UPD2(b.w, q * 4 + 3)
        }
#undef UPD1
#undef UPD2

        float soft_i1 = e[i1] * invs;
        float soft_i2 = e[i2] * invs;

        float uu = uin[grow * G_NUM + ggrp];
        float ww = wint[grow * G_NUM + ggrp];
        float v1 = (uu < 1.0f) ? ww : 1.0f;
        float v2 = (uu < 1.0f) ? (1.0f - ww) : 0.0f;
        float c1, c2;
        if (i1 == i2) { c1 = soft_i1 + ((v1 + v2) - soft_i1); c2 = 0.0f; }
        else          { c1 = soft_i1 + (v1 - soft_i1); c2 = soft_i2 + (v2 - soft_i2); }

        // record sampling result (dense materialization happens in copy-out)
        idx_s[row * 8 + gg] = i1 | (i2 << 8);
        cf2_s[(row * 8 + gg) * 2 + 0] = c1;
        cf2_s[(row * 8 + gg) * 2 + 1] = c2;

#pragma unroll
        for (int j = 0; j < 32; j++) Lp[j] = e[j] * invs;

        int slot = grow * G_NUM + ggrp;
        g_idx[slot] = i1 | (i2 << 8);
        g_coef[2 * slot + 0] = c1;
        g_coef[2 * slot + 1] = c2;

        // flag near-tie groups for exact sequential-fp32 recompute
        if (fminf(bv1 - bv1b, bv2 - bv2b) < TAU) {
            int fp = atomicAdd(&g_nfix, 1);
            if (fp < MAXFIX) g_fixlist[fp] = slot;
        }
    }
    __syncthreads();

    // -------- coalesced copy-out: soft from smem; sampled reconstructed from idx/coef --------
#pragma unroll
    for (int v = 0; v < 16; v++) {
        int u = v * 512 + tid;
        int row = u >> 6, q = u & 63;
        float4 sv;
        sv.x = Ls[row * LSTR + q * 4 + 0];
        sv.y = Ls[row * LSTR + q * 4 + 1];
        sv.z = Ls[row * LSTR + q * 4 + 2];
        sv.w = Ls[row * LSTR + q * 4 + 3];
        *(float4*)&out_soft[(size_t)(row0 + row) * C_DIM + col0 + q * 4] = sv;

        int gg = q >> 3;
        int pk = idx_s[row * 8 + gg];
        int i1 = pk & 255, i2 = (pk >> 8) & 255;
        float c1 = cf2_s[(row * 8 + gg) * 2 + 0];
        float c2 = cf2_s[(row * 8 + gg) * 2 + 1];
        int j0 = (q & 7) * 4;
        float4 sp;
        sp.x = ((j0 + 0 == i1) ? c1 : 0.0f) + ((j0 + 0 == i2) ? c2 : 0.0f);
        sp.y = ((j0 + 1 == i1) ? c1 : 0.0f) + ((j0 + 1 == i2) ? c2 : 0.0f);
        sp.z = ((j0 + 2 == i1) ? c1 : 0.0f) + ((j0 + 2 == i2) ? c2 : 0.0f);
        sp.w = ((j0 + 3 == i1) ? c1 : 0.0f) + ((j0 + 3 == i2) ? c2 : 0.0f);
        *(float4*)&out_sampled[(size_t)(row0 + row) * C_DIM + col0 + q * 4] = sp;
    }
}

// ---------------- K1b: exact sequential-fp32 recompute of flagged groups ----------------
#define WROWS 513
#define FIXSMEM ((512 + 32 * WROWS + 32) * 4)   // 67840
#define FIXGRID 2048

__global__ __launch_bounds__(256)
void k1b_fix(const float* __restrict__ x, const float* __restrict__ W1,
             const float* __restrict__ b1, const float* __restrict__ coff,
             const float* __restrict__ g1, const float* __restrict__ g2,
             const float* __restrict__ wint, const float* __restrict__ uin,
             float* __restrict__ out_sampled, float* __restrict__ out_soft) {
    extern __shared__ float fs[];
    float* xsh = fs;                    // [512]
    float* wsh = fs + 512;              // [32][513]
    float* sL  = fs + 512 + 32 * WROWS; // [32]

    int n = g_nfix;
    if (n > MAXFIX) n = MAXFIX;
    const int tid = threadIdx.x;

    for (int bi = blockIdx.x; bi < n; bi += FIXGRID) {
        __syncthreads();   // protect smem reuse across iterations
        const int slot = g_fixlist[bi];
        const int row  = slot >> 5;
        const int ggrp = slot & 31;
        const int gcol = ggrp * 32;

        for (int i = tid; i < 512 / 4; i += 256) {
            float4 v = *(const float4*)&x[(size_t)row * E_DIM + i * 4];
            xsh[i * 4 + 0] = v.x; xsh[i * 4 + 1] = v.y;
            xsh[i * 4 + 2] = v.z; xsh[i * 4 + 3] = v.w;
        }
        for (int u = tid; u < 32 * 128; u += 256) {
            int j = u >> 7, kq = u & 127;
            float4 v = *(const float4*)&W1[(size_t)(gcol + j) * E_DIM + kq * 4];
            wsh[j * WROWS + kq * 4 + 0] = v.x;
            wsh[j * WROWS + kq * 4 + 1] = v.y;
            wsh[j * WROWS + kq * 4 + 2] = v.z;
            wsh[j * WROWS + kq * 4 + 3] = v.w;
        }
        __syncthreads();

        if (tid < 32) {
            // exact sequential fp32 FMA chain, k = 0..511 (bitwise == the R6 path)
            const float* wr = wsh + tid * WROWS;
            float acc = 0.0f;
            for (int k = 0; k < 512; k++) acc = __fmaf_rn(xsh[k], wr[k], acc);
            sL[tid] = (acc + b1[gcol + tid]) * 3.0f + coff[gcol + tid];
        }
        __syncthreads();

        if (tid == 0) {
            float L[32];
#pragma unroll
            for (int j = 0; j < 32; j++) L[j] = sL[j];
            float m = -INFINITY;
#pragma unroll
            for (int j = 0; j < 32; j++) m = fmaxf(m, L[j]);
            float e[32];
            float s = 0.0f;
#pragma unroll
            for (int j = 0; j < 32; j++) { e[j] = expf(L[j] - m); s += e[j]; }
            float logs = logf(s);
            float invs = 1.0f / s;

            const float* G1 = &g1[(size_t)row * C_DIM + gcol];
            const float* G2 = &g2[(size_t)row * C_DIM + gcol];
            int i1 = 0, i2 = 0;
            float bv1 = -INFINITY, bv2 = -INFINITY;
#pragma unroll
            for (int j = 0; j < 32; j++) {
                float lp = (L[j] - m) - logs;
                float v = lp + G1[j]; if (v > bv1) { bv1 = v; i1 = j; }
                float u = lp + G2[j]; if (u > bv2) { bv2 = u; i2 = j; }
            }

            float soft_i1 = e[i1] * invs;
            float soft_i2 = e[i2] * invs;
            float uu = uin[row * G_NUM + ggrp];
            float ww = wint[row * G_NUM + ggrp];
            float v1 = (uu < 1.0f) ? ww : 1.0f;
            float v2 = (uu < 1.0f) ? (1.0f - ww) : 0.0f;
            float c1, c2;
            if (i1 == i2) { c1 = soft_i1 + ((v1 + v2) - soft_i1); c2 = 0.0f; }
            else          { c1 = soft_i1 + (v1 - soft_i1); c2 = soft_i2 + (v2 - soft_i2); }

#pragma unroll
            for (int j = 0; j < 32; j++) {
                out_soft[(size_t)row * C_DIM + gcol + j] = e[j] * invs;
                out_sampled[(size_t)row * C_DIM + gcol + j] =
                    ((j == i1) ? c1 : 0.0f) + ((j == i2 && i2 != i1) ? c2 : 0.0f);
            }
            g_idx[slot] = i1 | (i2 << 8);
            g_coef[2 * slot + 0] = c1;
            g_coef[2 * slot + 1] = c2;
        }
    }
}

// ---------------- K2: sparse projection (direct L1 gather) + LayerNorm ----------------
__global__ __launch_bounds__(512)
void k_proj_ln(const float* __restrict__ b2, const float* __restrict__ gamma,
               const float* __restrict__ beta,
               float* __restrict__ out_pos, float* __restrict__ out_neg) {
    const int tid = threadIdx.x;
    const int lane = tid & 31;
    const int wid  = tid >> 5;
    const int rowbase = blockIdx.x * 64;

    float4 h[4][4];
#pragma unroll
    for (int q = 0; q < 4; q++)
#pragma unroll
        for (int k = 0; k < 4; k++) h[q][k] = make_float4(0.f, 0.f, 0.f, 0.f);

#pragma unroll 1
    for (int g = 0; g < G_NUM; g++) {
#pragma unroll
        for (int q = 0; q < 4; q++) {
            int grow = rowbase + wid * 4 + q;
            int slot = grow * G_NUM + g;
            int packed = g_idx[slot];
            int i1 = packed & 255;
            int i2 = (packed >> 8) & 255;
            float c1 = g_coef[2 * slot + 0];
            float c2 = g_coef[2 * slot + 1];
            const float4* s1 = (const float4*)&g_W2T[(size_t)(g * CG_NUM + i1) * E_DIM];
            const float4* s2 = (const float4*)&g_W2T[(size_t)(g * CG_NUM + i2) * E_DIM];
#pragma unroll
            for (int k = 0; k < 4; k++) {
                float4 a = __ldg(&s1[lane + 32 * k]);
                float4 b = __ldg(&s2[lane + 32 * k]);
                h[q][k].x = fmaf(c1, a.x, fmaf(c2, b.x, h[q][k].x));
                h[q][k].y = fmaf(c1, a.y, fmaf(c2, b.y, h[q][k].y));
                h[q][k].z = fmaf(c1, a.z, fmaf(c2, b.z, h[q][k].z));
                h[q][k].w = fmaf(c1, a.w, fmaf(c2, b.w, h[q][k].w));
            }
        }
    }

    float4 b2r[4], gr[4], br[4];
#pragma unroll
    for (int k = 0; k < 4; k++) {
        b2r[k] = *(const float4*)&b2[lane * 4 + 128 * k];
        gr[k]  = *(const float4*)&gamma[lane * 4 + 128 * k];
        br[k]  = *(const float4*)&beta[lane * 4 + 128 * k];
    }

#pragma unroll
    for (int q = 0; q < 4; q++) {
        int grow = rowbase + wid * 4 + q;
        float sum = 0.0f;
#pragma unroll
        for (int k = 0; k < 4; k++) {
            h[q][k].x += b2r[k].x; h[q][k].y += b2r[k].y;
            h[q][k].z += b2r[k].z; h[q][k].w += b2r[k].w;
            sum += h[q][k].x + h[q][k].y + h[q][k].z + h[q][k].w;
        }
#pragma unroll
        for (int o = 16; o > 0; o >>= 1) sum += __shfl_xor_sync(0xffffffffu, sum, o);
        float mu = sum * (1.0f / 512.0f);
        float vs = 0.0f;
#pragma unroll
        for (int k = 0; k < 4; k++) {
            float dx;
            dx = h[q][k].x - mu; vs += dx * dx;
            dx = h[q][k].y - mu; vs += dx * dx;
            dx = h[q][k].z - mu; vs += dx * dx;
            dx = h[q][k].w - mu; vs += dx * dx;
        }
#pragma unroll
        for (int o = 16; o > 0; o >>= 1) vs += __shfl_xor_sync(0xffffffffu, vs, o);
        float var = vs * (1.0f / 512.0f);
        float sc = rsqrtf(var + 1e-5f);
#pragma unroll
        for (int k = 0; k < 4; k++) {
            float4 o4;
            o4.x = (h[q][k].x - mu) * sc * gr[k].x + br[k].x;
            o4.y = (h[q][k].y - mu) * sc * gr[k].y + br[k].y;
            o4.z = (h[q][k].z - mu) * sc * gr[k].z + br[k].z;
            o4.w = (h[q][k].w - mu) * sc * gr[k].w + br[k].w;
            int off = grow * E_DIM + lane * 4 + 128 * k;
            *(float4*)&out_pos[off] = o4;
            *(float4*)&out_neg[off] = o4;
        }
    }
}

extern "C" void kernel_launch(void* const* d_in, const int* in_sizes, int n_in,
                              void* d_out, int out_size) {
    const float* x     = (const float*)d_in[0];
    const float* W1    = (const float*)d_in[1];
    const float* b1    = (const float*)d_in[2];
    const float* coff  = (const float*)d_in[3];
    const float* W2    = (const float*)d_in[4];
    const float* b2    = (const float*)d_in[5];
    const float* gamma = (const float*)d_in[6];
    const float* beta  = (const float*)d_in[7];
    const float* g1    = (const float*)d_in[8];
    const float* g2    = (const float*)d_in[9];
    const float* wi    = (const float*)d_in[10];
    const float* ui    = (const float*)d_in[11];

    float* out = (float*)d_out;
    float* out_sampled = out;
    float* out_soft    = out + (size_t)SN * C_DIM;
    float* out_pos     = out + (size_t)2 * SN * C_DIM;
    float* out_neg     = out_pos + (size_t)SN * E_DIM;

    k_reset<<<1, 1>>>();
    k_split_x<<<SN * E_DIM / 1024, 256>>>(x);
    k_split_w<<<C_DIM * E_DIM / 1024, 256>>>(W1);
    k_transpose<<<dim3(32, 16), dim3(32, 8)>>>(W2);

    cudaFuncSetAttribute(k1_mma, cudaFuncAttributeMaxDynamicSharedMemorySize, SMEM_K1);
    k1_mma<<<dim3(C_DIM / BN, SN / BM), 512, SMEM_K1>>>(
        b1, coff, g1, g2, wi, ui, out_sampled, out_soft);

    cudaFuncSetAttribute(k1b_fix, cudaFuncAttributeMaxDynamicSharedMemorySize, FIXSMEM);
    k1b_fix<<<FIXGRID, 256, FIXSMEM>>>(x, W1, b1, coff, g1, g2, wi, ui,
                                       out_sampled, out_soft);

    cudaFuncSetAttribute(k_proj_ln, cudaFuncAttributePreferredSharedMemoryCarveout, 0);
    k_proj_ln<<<SN / 64, 512>>>(b2, gamma, beta, out_pos, out_neg);
}

// round 14
// speedup vs baseline: 1.6800x; 1.1391x over previous
#include <cuda_runtime.h>
#include <cuda_bf16.h>
#include <math.h>
#include <stdint.h>

#define SN     16384
#define E_DIM  512
#define C_DIM  1024
#define G_NUM  32
#define CG_NUM 32
#define MAXFIX 16384
#define TAU    1e-3f

// ---------------- scratch (static device globals: no runtime allocation) ----------------
__device__ __align__(16) __nv_bfloat16 g_xh[SN * E_DIM];
__device__ __align__(16) __nv_bfloat16 g_xl[SN * E_DIM];
__device__ __align__(16) __nv_bfloat16 g_wh[C_DIM * E_DIM];
__device__ __align__(16) __nv_bfloat16 g_wl[C_DIM * E_DIM];
__device__ float g_W2T[C_DIM * E_DIM];   // W2 transposed to (C, E)
__device__ int   g_idx[SN * G_NUM];      // packed argmax indices
__device__ float g_coef[SN * G_NUM * 2]; // straight-through coefficients
__device__ int   g_nfix;
__device__ int   g_fixlist[MAXFIX];

// ---------------- helpers ----------------
static __device__ __forceinline__ uint32_t smem_u32(const void* p) {
    uint32_t a;
    asm("{ .reg .u64 t; cvta.to.shared.u64 t, %1; cvt.u32.u64 %0, t; }" : "=r"(a) : "l"(p));
    return a;
}
static __device__ __forceinline__ void ldsm_x4(uint32_t* r, uint32_t addr) {
    asm volatile("ldmatrix.sync.aligned.m8n8.x4.shared.b16 {%0,%1,%2,%3}, [%4];"
        : "=r"(r[0]), "=r"(r[1]), "=r"(r[2]), "=r"(r[3]) : "r"(addr));
}
static __device__ __forceinline__ void mma_bf16(float* d, const uint32_t* a, const uint32_t* b) {
    asm volatile("mma.sync.aligned.m16n8k16.row.col.f32.bf16.bf16.f32 "
        "{%0,%1,%2,%3}, {%4,%5,%6,%7}, {%8,%9}, {%0,%1,%2,%3};"
        : "+f"(d[0]), "+f"(d[1]), "+f"(d[2]), "+f"(d[3])
        : "r"(a[0]), "r"(a[1]), "r"(a[2]), "r"(a[3]), "r"(b[0]), "r"(b[1]));
}
static __device__ __forceinline__ void cp16(uint32_t dst, const void* src) {
    asm volatile("cp.async.cg.shared.global [%0], [%1], 16;" :: "r"(dst), "l"(src));
}

__global__ void k_reset() { g_nfix = 0; }

// ---------------- split: fp32 -> bf16 double split ----------------
static __device__ __forceinline__ void split2(float x, __nv_bfloat16& a, __nv_bfloat16& b) {
    a = __float2bfloat16_rn(x);
    b = __float2bfloat16_rn(x - __bfloat162float(a));
}
__global__ void k_split_x(const float* __restrict__ src) {
    size_t i = ((size_t)blockIdx.x * 256 + threadIdx.x) * 4;
    float4 v = *(const float4*)(src + i);
    __nv_bfloat16 h[4], l[4];
    split2(v.x, h[0], l[0]); split2(v.y, h[1], l[1]);
    split2(v.z, h[2], l[2]); split2(v.w, h[3], l[3]);
    ((__nv_bfloat162*)(g_xh + i))[0] = __nv_bfloat162(h[0], h[1]);
    ((__nv_bfloat162*)(g_xh + i))[1] = __nv_bfloat162(h[2], h[3]);
    ((__nv_bfloat162*)(g_xl + i))[0] = __nv_bfloat162(l[0], l[1]);
    ((__nv_bfloat162*)(g_xl + i))[1] = __nv_bfloat162(l[2], l[3]);
}
__global__ void k_split_w(const float* __restrict__ src) {
    size_t i = ((size_t)blockIdx.x * 256 + threadIdx.x) * 4;
    float4 v = *(const float4*)(src + i);
    __nv_bfloat16 h[4], l[4];
    split2(v.x, h[0], l[0]); split2(v.y, h[1], l[1]);
    split2(v.z, h[2], l[2]); split2(v.w, h[3], l[3]);
    ((__nv_bfloat162*)(g_wh + i))[0] = __nv_bfloat162(h[0], h[1]);
    ((__nv_bfloat162*)(g_wh + i))[1] = __nv_bfloat162(h[2], h[3]);
    ((__nv_bfloat162*)(g_wl + i))[0] = __nv_bfloat162(l[0], l[1]);
    ((__nv_bfloat162*)(g_wl + i))[1] = __nv_bfloat162(l[2], l[3]);
}

// ---------------- K0: transpose W2 (E, C) -> g_W2T (C, E) ----------------
__global__ void k_transpose(const float* __restrict__ W2) {
    __shared__ float tile[32][33];
    const int bx = blockIdx.x, by = blockIdx.y;
    const int tx = threadIdx.x, ty = threadIdx.y;
#pragma unroll
    for (int j = 0; j < 4; j++)
        tile[ty + j * 8][tx] = W2[(by * 32 + ty + j * 8) * C_DIM + bx * 32 + tx];
    __syncthreads();
#pragma unroll
    for (int j = 0; j < 4; j++)
        g_W2T[(bx * 32 + ty + j * 8) * E_DIM + by * 32 + tx] = tile[tx][ty + j * 8];
}

// ---------------- K1a: warp-HMMA bf16x2 (3-product) GEMM, 2 CTAs/SM ----------------
#define BM 128
#define BN 128
#define KC 32
#define NCHUNK (E_DIM / KC)        // 16
#define AROW 80
#define ABUF (128 * AROW)          // 10240
#define BBUF (128 * AROW)          // 10240
#define BUFB (2 * ABUF + 2 * BBUF) // 40960 per stage
#define LSTR 131
#define SM_BIAS (2 * BUFB)         // 81920 (stages 81920 ∪ logits 67072)
#define SM_COF  (SM_BIAS + 512)
#define SM_IDX  (SM_COF + 512)     // int[128*4] = 2048
#define SM_CF2  (SM_IDX + 2048)    // float[128*4*2] = 4096
#define SMEM_K1 (SM_CF2 + 4096)    // 89088

__global__ __launch_bounds__(256, 2)
void k1_mma(const float* __restrict__ b1, const float* __restrict__ coff,
            const float* __restrict__ g1, const float* __restrict__ g2,
            const float* __restrict__ wint, const float* __restrict__ uin,
            float* __restrict__ out_sampled, float* __restrict__ out_soft) {
    extern __shared__ char smem[];
    const uint32_t sb = smem_u32(smem);
    const int tid = threadIdx.x;
    const int lane = tid & 31;
    const int wid = tid >> 5;              // 8 warps: wm = wid>>1 (0..3), wn = wid&1
    const int wm = wid >> 1, wn = wid & 1;
    const int row0 = blockIdx.y * BM;
    const int col0 = blockIdx.x * BN;
    float* b1s = (float*)(smem + SM_BIAS);
    float* cfs = (float*)(smem + SM_COF);
    int*   idx_s = (int*)(smem + SM_IDX);
    float* cf2_s = (float*)(smem + SM_CF2);

    if (tid < 128) { b1s[tid] = b1[col0 + tid]; cfs[tid] = coff[col0 + tid]; }

    float acc[2][8][4];
#pragma unroll
    for (int mt = 0; mt < 2; mt++)
#pragma unroll
        for (int nt = 0; nt < 8; nt++)
#pragma unroll
            for (int k = 0; k < 4; k++) acc[mt][nt][k] = 0.0f;

    const __nv_bfloat16* xs[2] = { g_xh, g_xl };
    const __nv_bfloat16* ws[2] = { g_wh, g_wl };

    auto load_chunk = [&](int c, int b) {
        const int kk = c * KC;
#pragma unroll
        for (int p = 0; p < 4; p++) {          // A: 2 splits x 128 rows x 4 x16B
            int u = p * 256 + tid;
            int split = u >> 9;
            int rem = u & 511;
            int row = rem >> 2, c16 = rem & 3;
            cp16(sb + b * BUFB + split * ABUF + row * AROW + c16 * 16,
                 xs[split] + (size_t)(row0 + row) * E_DIM + kk + c16 * 8);
        }
#pragma unroll
        for (int p = 0; p < 4; p++) {          // B: 2 splits x 128 rows x 4 x16B
            int u = p * 256 + tid;
            int split = u >> 9;
            int rem = u & 511;
            int row = rem >> 2, c16 = rem & 3;
            cp16(sb + b * BUFB + 2 * ABUF + split * BBUF + row * AROW + c16 * 16,
                 ws[split] + (size_t)(col0 + row) * E_DIM + kk + c16 * 8);
        }
        asm volatile("cp.async.commit_group;" ::: "memory");
    };

    load_chunk(0, 0);
    for (int c = 0; c < NCHUNK; c++) {
        const int b = c & 1;
        if (c + 1 < NCHUNK) {
            load_chunk(c + 1, b ^ 1);
            asm volatile("cp.async.wait_group 1;" ::: "memory");
        } else {
            asm volatile("cp.async.wait_group 0;" ::: "memory");
        }
        __syncthreads();

        const int r = lane & 7, blk = lane >> 3;
        const int am_off = (blk & 1) * 8 + r;
        const int ak_off = (blk >> 1) * 8;
        const int bn_off = (blk >> 1) * 8 + r;
        const int bk_off = (blk & 1) * 8;
#pragma unroll
        for (int kss = 0; kss < 2; kss++) {
            uint32_t afr[2][2][4];
#pragma unroll
            for (int s = 0; s < 2; s++)
#pragma unroll
                for (int mt = 0; mt < 2; mt++)
                    ldsm_x4(afr[s][mt], sb + b * BUFB + s * ABUF
                            + (wm * 32 + mt * 16 + am_off) * AROW + (kss * 16 + ak_off) * 2);
#pragma unroll
            for (int np = 0; np < 4; np++) {
                uint32_t bfr[2][4];
#pragma unroll
                for (int s = 0; s < 2; s++)
                    ldsm_x4(bfr[s], sb + b * BUFB + 2 * ABUF + s * BBUF
                            + (wn * 64 + np * 16 + bn_off) * AROW + (kss * 16 + bk_off) * 2);
#pragma unroll
                for (int mt = 0; mt < 2; mt++)
#pragma unroll
                    for (int nt = 0; nt < 2; nt++) {
                        float* ac = acc[mt][np * 2 + nt];
                        mma_bf16(ac, afr[0][mt], &bfr[0][nt * 2]);   // hh
                        mma_bf16(ac, afr[0][mt], &bfr[1][nt * 2]);   // hl
                        mma_bf16(ac, afr[1][mt], &bfr[0][nt * 2]);   // lh
                    }
            }
        }
        __syncthreads();
    }

    // -------- logits (reference order) to smem --------
    float* Ls = (float*)smem;
    const int r0l = lane >> 2, c0l = (lane & 3) * 2;
#pragma unroll
    for (int mt = 0; mt < 2; mt++)
#pragma unroll
        for (int nt = 0; nt < 8; nt++) {
            int row = wm * 32 + mt * 16 + r0l;
            int col = wn * 64 + nt * 8 + c0l;
            Ls[row * LSTR + col]           = (acc[mt][nt][0] + b1s[col])     * 3.0f + cfs[col];
            Ls[row * LSTR + col + 1]       = (acc[mt][nt][1] + b1s[col + 1]) * 3.0f + cfs[col + 1];
            Ls[(row + 8) * LSTR + col]     = (acc[mt][nt][2] + b1s[col])     * 3.0f + cfs[col];
            Ls[(row + 8) * LSTR + col + 1] = (acc[mt][nt][3] + b1s[col + 1]) * 3.0f + cfs[col + 1];
        }
    __syncthreads();

    // -------- per-(row, group) softmax + Gumbel sampling + gap flagging --------
#pragma unroll 1
    for (int p = 0; p < 2; p++) {
        const int task = p * 256 + tid;
        const int row = task & 127;
        const int gg  = task >> 7;             // 0..3
        const int grow = row0 + row;
        const int gcol = col0 + gg * CG_NUM;
        const int ggrp = gcol >> 5;
        float* Lp = &Ls[row * LSTR + gg * CG_NUM];

        float L[32];
#pragma unroll
        for (int j = 0; j < 32; j++) L[j] = Lp[j];

        float m = -INFINITY;
#pragma unroll
        for (int j = 0; j < 32; j++) m = fmaxf(m, L[j]);
        float e[32];
        float s = 0.0f;
#pragma unroll
        for (int j = 0; j < 32; j++) { e[j] = expf(L[j] - m); s += e[j]; }
        float logs = logf(s);
        float invs = 1.0f / s;

        const float4* G1 = (const float4*)&g1[(size_t)grow * C_DIM + gcol];
        const float4* G2 = (const float4*)&g2[(size_t)grow * C_DIM + gcol];
        int i1 = 0, i2 = 0;
        float bv1 = -INFINITY, bv2 = -INFINITY;
        float bv1b = -INFINITY, bv2b = -INFINITY;
#define UPD1(val, idx) { float v = lp + (val); if (v > bv1) { bv1b = bv1; bv1 = v; i1 = (idx); } else if (v > bv1b) bv1b = v; }
#define UPD2(val, idx) { float u = lp + (val); if (u > bv2) { bv2b = bv2; bv2 = u; i2 = (idx); } else if (u > bv2b) bv2b = u; }
#pragma unroll
        for (int q = 0; q < 8; q++) {
            float4 a = G1[q];
            float4 b = G2[q];
            float lp;
            lp = (L[q * 4 + 0] - m) - logs; UPD1(a.x, q * 4 + 0) UPD2(b.x, q * 4 + 0)
            lp = (L[q * 4 + 1] - m) - logs; UPD1(a.y, q * 4 + 1) UPD2(b.y, q * 4 + 1)
            lp = (L[q * 4 + 2] - m) - logs; UPD1(a.z, q * 4 + 2) UPD2(b.z, q * 4 + 2)
            lp = (L[q * 4 + 3] - m) - logs; UPD1(a.w, q * 4 + 3) UPD2(b.w, q * 4 + 3)
        }
#undef UPD1
#undef UPD2

        float soft_i1 = e[i1] * invs;
        float soft_i2 = e[i2] * invs;

        float uu = uin[grow * G_NUM + ggrp];
        float ww = wint[grow * G_NUM + ggrp];
        float v1 = (uu < 1.0f) ? ww : 1.0f;
        float v2 = (uu < 1.0f) ? (1.0f - ww) : 0.0f;
        float c1, c2;
        if (i1 == i2) { c1 = soft_i1 + ((v1 + v2) - soft_i1); c2 = 0.0f; }
        else          { c1 = soft_i1 + (v1 - soft_i1); c2 = soft_i2 + (v2 - soft_i2); }

        // record sampling result (dense materialization happens in copy-out)
        idx_s[row * 4 + gg] = i1 | (i2 << 8);
        cf2_s[(row * 4 + gg) * 2 + 0] = c1;
        cf2_s[(row * 4 + gg) * 2 + 1] = c2;

#pragma unroll
        for (int j = 0; j < 32; j++) Lp[j] = e[j] * invs;

        int slot = grow * G_NUM + ggrp;
        g_idx[slot] = i1 | (i2 << 8);
        g_coef[2 * slot + 0] = c1;
        g_coef[2 * slot + 1] = c2;

        // flag near-tie groups for exact sequential-fp32 recompute
        if (fminf(bv1 - bv1b, bv2 - bv2b) < TAU) {
            int fp = atomicAdd(&g_nfix, 1);
            if (fp < MAXFIX) g_fixlist[fp] = slot;
        }
    }
    __syncthreads();

    // -------- coalesced copy-out: soft from smem; sampled reconstructed from idx/coef --------
#pragma unroll
    for (int v = 0; v < 16; v++) {
        int u = v * 256 + tid;
        int row = u >> 5, q = u & 31;
        float4 sv;
        sv.x = Ls[row * LSTR + q * 4 + 0];
        sv.y = Ls[row * LSTR + q * 4 + 1];
        sv.z = Ls[row * LSTR + q * 4 + 2];
        sv.w = Ls[row * LSTR + q * 4 + 3];
        *(float4*)&out_soft[(size_t)(row0 + row) * C_DIM + col0 + q * 4] = sv;

        int gg = q >> 3;
        int pk = idx_s[row * 4 + gg];
        int i1 = pk & 255, i2 = (pk >> 8) & 255;
        float c1 = cf2_s[(row * 4 + gg) * 2 + 0];
        float c2 = cf2_s[(row * 4 + gg) * 2 + 1];
        int j0 = (q & 7) * 4;
        float4 sp;
        sp.x = ((j0 + 0 == i1) ? c1 : 0.0f) + ((j0 + 0 == i2) ? c2 : 0.0f);
        sp.y = ((j0 + 1 == i1) ? c1 : 0.0f) + ((j0 + 1 == i2) ? c2 : 0.0f);
        sp.z = ((j0 + 2 == i1) ? c1 : 0.0f) + ((j0 + 2 == i2) ? c2 : 0.0f);
        sp.w = ((j0 + 3 == i1) ? c1 : 0.0f) + ((j0 + 3 == i2) ? c2 : 0.0f);
        *(float4*)&out_sampled[(size_t)(row0 + row) * C_DIM + col0 + q * 4] = sp;
    }
}

// ---------------- K1b: exact sequential-fp32 recompute of flagged groups ----------------
#define WROWS 513
#define FIXSMEM ((512 + 32 * WROWS + 32) * 4)   // 67840
#define FIXGRID 2048

__global__ __launch_bounds__(256)
void k1b_fix(const float* __restrict__ x, const float* __restrict__ W1,
             const float* __restrict__ b1, const float* __restrict__ coff,
             const float* __restrict__ g1, const float* __restrict__ g2,
             const float* __restrict__ wint, const float* __restrict__ uin,
             float* __restrict__ out_sampled, float* __restrict__ out_soft) {
    extern __shared__ float fs[];
    float* xsh = fs;                    // [512]
    float* wsh = fs + 512;              // [32][513]
    float* sL  = fs + 512 + 32 * WROWS; // [32]

    int n = g_nfix;
    if (n > MAXFIX) n = MAXFIX;
    const int tid = threadIdx.x;

    for (int bi = blockIdx.x; bi < n; bi += FIXGRID) {
        __syncthreads();   // protect smem reuse across iterations
        const int slot = g_fixlist[bi];
        const int row  = slot >> 5;
        const int ggrp = slot & 31;
        const int gcol = ggrp * 32;

        for (int i = tid; i < 512 / 4; i += 256) {
            float4 v = *(const float4*)&x[(size_t)row * E_DIM + i * 4];
            xsh[i * 4 + 0] = v.x; xsh[i * 4 + 1] = v.y;
            xsh[i * 4 + 2] = v.z; xsh[i * 4 + 3] = v.w;
        }
        for (int u = tid; u < 32 * 128; u += 256) {
            int j = u >> 7, kq = u & 127;
            float4 v = *(const float4*)&W1[(size_t)(gcol + j) * E_DIM + kq * 4];
            wsh[j * WROWS + kq * 4 + 0] = v.x;
            wsh[j * WROWS + kq * 4 + 1] = v.y;
            wsh[j * WROWS + kq * 4 + 2] = v.z;
            wsh[j * WROWS + kq * 4 + 3] = v.w;
        }
        __syncthreads();

        if (tid < 32) {
            // exact sequential fp32 FMA chain, k = 0..511 (bitwise == the R6 path)
            const float* wr = wsh + tid * WROWS;
            float acc = 0.0f;
            for (int k = 0; k < 512; k++) acc = __fmaf_rn(xsh[k], wr[k], acc);
            sL[tid] = (acc + b1[gcol + tid]) * 3.0f + coff[gcol + tid];
        }
        __syncthreads();

        if (tid == 0) {
            float L[32];
#pragma unroll
            for (int j = 0; j < 32; j++) L[j] = sL[j];
            float m = -INFINITY;
#pragma unroll
            for (int j = 0; j < 32; j++) m = fmaxf(m, L[j]);
            float e[32];
            float s = 0.0f;
#pragma unroll
            for (int j = 0; j < 32; j++) { e[j] = expf(L[j] - m); s += e[j]; }
            float logs = logf(s);
            float invs = 1.0f / s;

            const float* G1 = &g1[(size_t)row * C_DIM + gcol];
            const float* G2 = &g2[(size_t)row * C_DIM + gcol];
            int i1 = 0, i2 = 0;
            float bv1 = -INFINITY, bv2 = -INFINITY;
#pragma unroll
            for (int j = 0; j < 32; j++) {
                float lp = (L[j] - m) - logs;
                float v = lp + G1[j]; if (v > bv1) { bv1 = v; i1 = j; }
                float u = lp + G2[j]; if (u > bv2) { bv2 = u; i2 = j; }
            }

            float soft_i1 = e[i1] * invs;
            float soft_i2 = e[i2] * invs;
            float uu = uin[row * G_NUM + ggrp];
            float ww = wint[row * G_NUM + ggrp];
            float v1 = (uu < 1.0f) ? ww : 1.0f;
            float v2 = (uu < 1.0f) ? (1.0f - ww) : 0.0f;
            float c1, c2;
            if (i1 == i2) { c1 = soft_i1 + ((v1 + v2) - soft_i1); c2 = 0.0f; }
            else          { c1 = soft_i1 + (v1 - soft_i1); c2 = soft_i2 + (v2 - soft_i2); }

#pragma unroll
            for (int j = 0; j < 32; j++) {
                out_soft[(size_t)row * C_DIM + gcol + j] = e[j] * invs;
                out_sampled[(size_t)row * C_DIM + gcol + j] =
                    ((j == i1) ? c1 : 0.0f) + ((j == i2 && i2 != i1) ? c2 : 0.0f);
            }
            g_idx[slot] = i1 | (i2 << 8);
            g_coef[2 * slot + 0] = c1;
            g_coef[2 * slot + 1] = c2;
        }
    }
}

// ---------------- K2: sparse projection (direct L1 gather) + LayerNorm ----------------
__global__ __launch_bounds__(512)
void k_proj_ln(const float* __restrict__ b2, const float* __restrict__ gamma,
               const float* __restrict__ beta,
               float* __restrict__ out_pos, float* __restrict__ out_neg) {
    const int tid = threadIdx.x;
    const int lane = tid & 31;
    const int wid  = tid >> 5;
    const int rowbase = blockIdx.x * 64;

    float4 h[4][4];
#pragma unroll
    for (int q = 0; q < 4; q++)
#pragma unroll
        for (int k = 0; k < 4; k++) h[q][k] = make_float4(0.f, 0.f, 0.f, 0.f);

#pragma unroll 1
    for (int g = 0; g < G_NUM; g++) {
#pragma unroll
        for (int q = 0; q < 4; q++) {
            int grow = rowbase + wid * 4 + q;
            int slot = grow * G_NUM + g;
            int packed = g_idx[slot];
            int i1 = packed & 255;
            int i2 = (packed >> 8) & 255;
            float c1 = g_coef[2 * slot + 0];
            float c2 = g_coef[2 * slot + 1];
            const float4* s1 = (const float4*)&g_W2T[(size_t)(g * CG_NUM + i1) * E_DIM];
            const float4* s2 = (const float4*)&g_W2T[(size_t)(g * CG_NUM + i2) * E_DIM];
#pragma unroll
            for (int k = 0; k < 4; k++) {
                float4 a = __ldg(&s1[lane + 32 * k]);
                float4 b = __ldg(&s2[lane + 32 * k]);
                h[q][k].x = fmaf(c1, a.x, fmaf(c2, b.x, h[q][k].x));
                h[q][k].y = fmaf(c1, a.y, fmaf(c2, b.y, h[q][k].y));
                h[q][k].z = fmaf(c1, a.z, fmaf(c2, b.z, h[q][k].z));
                h[q][k].w = fmaf(c1, a.w, fmaf(c2, b.w, h[q][k].w));
            }
        }
    }

    float4 b2r[4], gr[4], br[4];
#pragma unroll
    for (int k = 0; k < 4; k++) {
        b2r[k] = *(const float4*)&b2[lane * 4 + 128 * k];
        gr[k]  = *(const float4*)&gamma[lane * 4 + 128 * k];
        br[k]  = *(const float4*)&beta[lane * 4 + 128 * k];
    }

#pragma unroll
    for (int q = 0; q < 4; q++) {
        int grow = rowbase + wid * 4 + q;
        float sum = 0.0f;
#pragma unroll
        for (int k = 0; k < 4; k++) {
            h[q][k].x += b2r[k].x; h[q][k].y += b2r[k].y;
            h[q][k].z += b2r[k].z; h[q][k].w += b2r[k].w;
            sum += h[q][k].x + h[q][k].y + h[q][k].z + h[q][k].w;
        }
#pragma unroll
        for (int o = 16; o > 0; o >>= 1) sum += __shfl_xor_sync(0xffffffffu, sum, o);
        float mu = sum * (1.0f / 512.0f);
        float vs = 0.0f;
#pragma unroll
        for (int k = 0; k < 4; k++) {
            float dx;
            dx = h[q][k].x - mu; vs += dx * dx;
            dx = h[q][k].y - mu; vs += dx * dx;
            dx = h[q][k].z - mu; vs += dx * dx;
            dx = h[q][k].w - mu; vs += dx * dx;
        }
#pragma unroll
        for (int o = 16; o > 0; o >>= 1) vs += __shfl_xor_sync(0xffffffffu, vs, o);
        float var = vs * (1.0f / 512.0f);
        float sc = rsqrtf(var + 1e-5f);
#pragma unroll
        for (int k = 0; k < 4; k++) {
            float4 o4;
            o4.x = (h[q][k].x - mu) * sc * gr[k].x + br[k].x;
            o4.y = (h[q][k].y - mu) * sc * gr[k].y + br[k].y;
            o4.z = (h[q][k].z - mu) * sc * gr[k].z + br[k].z;
            o4.w = (h[q][k].w - mu) * sc * gr[k].w + br[k].w;
            int off = grow * E_DIM + lane * 4 + 128 * k;
            *(float4*)&out_pos[off] = o4;
            *(float4*)&out_neg[off] = o4;
        }
    }
}

extern "C" void kernel_launch(void* const* d_in, const int* in_sizes, int n_in,
                              void* d_out, int out_size) {
    const float* x     = (const float*)d_in[0];
    const float* W1    = (const float*)d_in[1];
    const float* b1    = (const float*)d_in[2];
    const float* coff  = (const float*)d_in[3];
    const float* W2    = (const float*)d_in[4];
    const float* b2    = (const float*)d_in[5];
    const float* gamma = (const float*)d_in[6];
    const float* beta  = (const float*)d_in[7];
    const float* g1    = (const float*)d_in[8];
    const float* g2    = (const float*)d_in[9];
    const float* wi    = (const float*)d_in[10];
    const float* ui    = (const float*)d_in[11];

    float* out = (float*)d_out;
    float* out_sampled = out;
    float* out_soft    = out + (size_t)SN * C_DIM;
    float* out_pos     = out + (size_t)2 * SN * C_DIM;
    float* out_neg     = out_pos + (size_t)SN * E_DIM;

    k_reset<<<1, 1>>>();
    k_split_x<<<SN * E_DIM / 1024, 256>>>(x);
    k_split_w<<<C_DIM * E_DIM / 1024, 256>>>(W1);
    k_transpose<<<dim3(32, 16), dim3(32, 8)>>>(W2);

    cudaFuncSetAttribute(k1_mma, cudaFuncAttributeMaxDynamicSharedMemorySize, SMEM_K1);
    k1_mma<<<dim3(C_DIM / BN, SN / BM), 256, SMEM_K1>>>(
        b1, coff, g1, g2, wi, ui, out_sampled, out_soft);

    cudaFuncSetAttribute(k1b_fix, cudaFuncAttributeMaxDynamicSharedMemorySize, FIXSMEM);
    k1b_fix<<<FIXGRID, 256, FIXSMEM>>>(x, W1, b1, coff, g1, g2, wi, ui,
                                       out_sampled, out_soft);

    cudaFuncSetAttribute(k_proj_ln, cudaFuncAttributePreferredSharedMemoryCarveout, 0);
    k_proj_ln<<<SN / 64, 512>>>(b2, gamma, beta, out_pos, out_neg);
}

// round 15
// speedup vs baseline: 1.6908x; 1.0065x over previous
#include <cuda_runtime.h>
#include <cuda_bf16.h>
#include <math.h>
#include <stdint.h>

#define SN     16384
#define E_DIM  512
#define C_DIM  1024
#define G_NUM  32
#define CG_NUM 32
#define MAXFIX 16384
#define TAU    1e-3f

// ---------------- scratch (static device globals: no runtime allocation) ----------------
__device__ __align__(16) __nv_bfloat16 g_xh[SN * E_DIM];
__device__ __align__(16) __nv_bfloat16 g_xl[SN * E_DIM];
__device__ __align__(16) __nv_bfloat16 g_wh[C_DIM * E_DIM];
__device__ __align__(16) __nv_bfloat16 g_wl[C_DIM * E_DIM];
__device__ float g_W2T[C_DIM * E_DIM];   // W2 transposed to (C, E)
__device__ int   g_idx[SN * G_NUM];      // packed argmax indices
__device__ float g_coef[SN * G_NUM * 2]; // straight-through coefficients
__device__ int   g_nfix;
__device__ int   g_fixlist[MAXFIX];

// ---------------- helpers ----------------
static __device__ __forceinline__ uint32_t smem_u32(const void* p) {
    uint32_t a;
    asm("{ .reg .u64 t; cvta.to.shared.u64 t, %1; cvt.u32.u64 %0, t; }" : "=r"(a) : "l"(p));
    return a;
}
static __device__ __forceinline__ void ldsm_x4(uint32_t* r, uint32_t addr) {
    asm volatile("ldmatrix.sync.aligned.m8n8.x4.shared.b16 {%0,%1,%2,%3}, [%4];"
        : "=r"(r[0]), "=r"(r[1]), "=r"(r[2]), "=r"(r[3]) : "r"(addr));
}
static __device__ __forceinline__ void mma_bf16(float* d, const uint32_t* a, const uint32_t* b) {
    asm volatile("mma.sync.aligned.m16n8k16.row.col.f32.bf16.bf16.f32 "
        "{%0,%1,%2,%3}, {%4,%5,%6,%7}, {%8,%9}, {%0,%1,%2,%3};"
        : "+f"(d[0]), "+f"(d[1]), "+f"(d[2]), "+f"(d[3])
        : "r"(a[0]), "r"(a[1]), "r"(a[2]), "r"(a[3]), "r"(b[0]), "r"(b[1]));
}
static __device__ __forceinline__ void cp16(uint32_t dst, const void* src) {
    asm volatile("cp.async.cg.shared.global [%0], [%1], 16;" :: "r"(dst), "l"(src));
}

// ---------------- split: fp32 -> bf16 double split ----------------
static __device__ __forceinline__ void split2(float x, __nv_bfloat16& a, __nv_bfloat16& b) {
    a = __float2bfloat16_rn(x);
    b = __float2bfloat16_rn(x - __bfloat162float(a));
}
__global__ void k_split_x(const float* __restrict__ src) {
    if (blockIdx.x == 0 && threadIdx.x == 0) g_nfix = 0;   // fused reset
    size_t i = ((size_t)blockIdx.x * 256 + threadIdx.x) * 4;
    float4 v = *(const float4*)(src + i);
    __nv_bfloat16 h[4], l[4];
    split2(v.x, h[0], l[0]); split2(v.y, h[1], l[1]);
    split2(v.z, h[2], l[2]); split2(v.w, h[3], l[3]);
    ((__nv_bfloat162*)(g_xh + i))[0] = __nv_bfloat162(h[0], h[1]);
    ((__nv_bfloat162*)(g_xh + i))[1] = __nv_bfloat162(h[2], h[3]);
    ((__nv_bfloat162*)(g_xl + i))[0] = __nv_bfloat162(l[0], l[1]);
    ((__nv_bfloat162*)(g_xl + i))[1] = __nv_bfloat162(l[2], l[3]);
}
__global__ void k_split_w(const float* __restrict__ src) {
    size_t i = ((size_t)blockIdx.x * 256 + threadIdx.x) * 4;
    float4 v = *(const float4*)(src + i);
    __nv_bfloat16 h[4], l[4];
    split2(v.x, h[0], l[0]); split2(v.y, h[1], l[1]);
    split2(v.z, h[2], l[2]); split2(v.w, h[3], l[3]);
    ((__nv_bfloat162*)(g_wh + i))[0] = __nv_bfloat162(h[0], h[1]);
    ((__nv_bfloat162*)(g_wh + i))[1] = __nv_bfloat162(h[2], h[3]);
    ((__nv_bfloat162*)(g_wl + i))[0] = __nv_bfloat162(l[0], l[1]);
    ((__nv_bfloat162*)(g_wl + i))[1] = __nv_bfloat162(l[2], l[3]);
}

// ---------------- K0: transpose W2 (E, C) -> g_W2T (C, E) ----------------
__global__ void k_transpose(const float* __restrict__ W2) {
    __shared__ float tile[32][33];
    const int bx = blockIdx.x, by = blockIdx.y;
    const int tx = threadIdx.x, ty = threadIdx.y;
#pragma unroll
    for (int j = 0; j < 4; j++)
        tile[ty + j * 8][tx] = W2[(by * 32 + ty + j * 8) * C_DIM + bx * 32 + tx];
    __syncthreads();
#pragma unroll
    for (int j = 0; j < 4; j++)
        g_W2T[(bx * 32 + ty + j * 8) * E_DIM + by * 32 + tx] = tile[tx][ty + j * 8];
}

// ---------------- K1a: warp-HMMA bf16x2 (3-product) GEMM, 2 CTAs/SM ----------------
#define BM 128
#define BN 128
#define KC 32
#define NCHUNK (E_DIM / KC)        // 16
#define AROW 80
#define ABUF (128 * AROW)          // 10240
#define BBUF (128 * AROW)          // 10240
#define BUFB (2 * ABUF + 2 * BBUF) // 40960 per stage
#define LSTR 131
#define SM_BIAS (2 * BUFB)         // 81920 (stages 81920 ∪ logits 67072)
#define SM_COF  (SM_BIAS + 512)
#define SM_IDX  (SM_COF + 512)     // int[128*4] = 2048
#define SM_CF2  (SM_IDX + 2048)    // float[128*4*2] = 4096
#define SMEM_K1 (SM_CF2 + 4096)    // 89088

__global__ __launch_bounds__(256, 2)
void k1_mma(const float* __restrict__ b1, const float* __restrict__ coff,
            const float* __restrict__ g1, const float* __restrict__ g2,
            const float* __restrict__ wint, const float* __restrict__ uin,
            float* __restrict__ out_sampled, float* __restrict__ out_soft) {
    extern __shared__ char smem[];
    const uint32_t sb = smem_u32(smem);
    const int tid = threadIdx.x;
    const int lane = tid & 31;
    const int wid = tid >> 5;              // 8 warps: wm = wid>>1 (0..3), wn = wid&1
    const int wm = wid >> 1, wn = wid & 1;
    const int row0 = blockIdx.y * BM;
    const int col0 = blockIdx.x * BN;
    float* b1s = (float*)(smem + SM_BIAS);
    float* cfs = (float*)(smem + SM_COF);
    int*   idx_s = (int*)(smem + SM_IDX);
    float* cf2_s = (float*)(smem + SM_CF2);

    if (tid < 128) { b1s[tid] = b1[col0 + tid]; cfs[tid] = coff[col0 + tid]; }

    float acc[2][8][4];
#pragma unroll
    for (int mt = 0; mt < 2; mt++)
#pragma unroll
        for (int nt = 0; nt < 8; nt++)
#pragma unroll
            for (int k = 0; k < 4; k++) acc[mt][nt][k] = 0.0f;

    const __nv_bfloat16* xs[2] = { g_xh, g_xl };
    const __nv_bfloat16* ws[2] = { g_wh, g_wl };

    auto load_chunk = [&](int c, int b) {
        const int kk = c * KC;
#pragma unroll
        for (int p = 0; p < 4; p++) {          // A: 2 splits x 128 rows x 4 x16B
            int u = p * 256 + tid;
            int split = u >> 9;
            int rem = u & 511;
            int row = rem >> 2, c16 = rem & 3;
            cp16(sb + b * BUFB + split * ABUF + row * AROW + c16 * 16,
                 xs[split] + (size_t)(row0 + row) * E_DIM + kk + c16 * 8);
        }
#pragma unroll
        for (int p = 0; p < 4; p++) {          // B: 2 splits x 128 rows x 4 x16B
            int u = p * 256 + tid;
            int split = u >> 9;
            int rem = u & 511;
            int row = rem >> 2, c16 = rem & 3;
            cp16(sb + b * BUFB + 2 * ABUF + split * BBUF + row * AROW + c16 * 16,
                 ws[split] + (size_t)(col0 + row) * E_DIM + kk + c16 * 8);
        }
        asm volatile("cp.async.commit_group;" ::: "memory");
    };

    load_chunk(0, 0);
    for (int c = 0; c < NCHUNK; c++) {
        const int b = c & 1;
        if (c + 1 < NCHUNK) {
            load_chunk(c + 1, b ^ 1);
            asm volatile("cp.async.wait_group 1;" ::: "memory");
        } else {
            asm volatile("cp.async.wait_group 0;" ::: "memory");
        }
        __syncthreads();

        const int r = lane & 7, blk = lane >> 3;
        const int am_off = (blk & 1) * 8 + r;
        const int ak_off = (blk >> 1) * 8;
        const int bn_off = (blk >> 1) * 8 + r;
        const int bk_off = (blk & 1) * 8;
#pragma unroll
        for (int kss = 0; kss < 2; kss++) {
            uint32_t afr[2][2][4];
#pragma unroll
            for (int s = 0; s < 2; s++)
#pragma unroll
                for (int mt = 0; mt < 2; mt++)
                    ldsm_x4(afr[s][mt], sb + b * BUFB + s * ABUF
                            + (wm * 32 + mt * 16 + am_off) * AROW + (kss * 16 + ak_off) * 2);
#pragma unroll
            for (int np = 0; np < 4; np++) {
                uint32_t bfr[2][4];
#pragma unroll
                for (int s = 0; s < 2; s++)
                    ldsm_x4(bfr[s], sb + b * BUFB + 2 * ABUF + s * BBUF
                            + (wn * 64 + np * 16 + bn_off) * AROW + (kss * 16 + bk_off) * 2);
#pragma unroll
                for (int mt = 0; mt < 2; mt++)
#pragma unroll
                    for (int nt = 0; nt < 2; nt++) {
                        float* ac = acc[mt][np * 2 + nt];
                        mma_bf16(ac, afr[0][mt], &bfr[0][nt * 2]);   // hh
                        mma_bf16(ac, afr[0][mt], &bfr[1][nt * 2]);   // hl
                        mma_bf16(ac, afr[1][mt], &bfr[0][nt * 2]);   // lh
                    }
            }
        }
        __syncthreads();
    }

    // -------- logits (reference order) to smem --------
    float* Ls = (float*)smem;
    const int r0l = lane >> 2, c0l = (lane & 3) * 2;
#pragma unroll
    for (int mt = 0; mt < 2; mt++)
#pragma unroll
        for (int nt = 0; nt < 8; nt++) {
            int row = wm * 32 + mt * 16 + r0l;
            int col = wn * 64 + nt * 8 + c0l;
            Ls[row * LSTR + col]           = (acc[mt][nt][0] + b1s[col])     * 3.0f + cfs[col];
            Ls[row * LSTR + col + 1]       = (acc[mt][nt][1] + b1s[col + 1]) * 3.0f + cfs[col + 1];
            Ls[(row + 8) * LSTR + col]     = (acc[mt][nt][2] + b1s[col])     * 3.0f + cfs[col];
            Ls[(row + 8) * LSTR + col + 1] = (acc[mt][nt][3] + b1s[col + 1]) * 3.0f + cfs[col + 1];
        }
    __syncthreads();

    // -------- per-(row, group) softmax + Gumbel sampling + gap flagging --------
    // NOTE: __expf/__logf are safe here: m and logs shift all classes in a group
    // uniformly, so argmax decisions and flag gaps are invariant to exp/log error;
    // c1/c2 collapse algebraically to v1/v2 (soft cancels); only out_soft values
    // carry the ~1e-6 MUFU error, well under the 1e-3 budget.
#pragma unroll 1
    for (int p = 0; p < 2; p++) {
        const int task = p * 256 + tid;
        const int row = task & 127;
        const int gg  = task >> 7;             // 0..3
        const int grow = row0 + row;
        const int gcol = col0 + gg * CG_NUM;
        const int ggrp = gcol >> 5;
        float* Lp = &Ls[row * LSTR + gg * CG_NUM];

        float L[32];
#pragma unroll
        for (int j = 0; j < 32; j++) L[j] = Lp[j];

        float m = -INFINITY;
#pragma unroll
        for (int j = 0; j < 32; j++) m = fmaxf(m, L[j]);
        float e[32];
        float s = 0.0f;
#pragma unroll
        for (int j = 0; j < 32; j++) { e[j] = __expf(L[j] - m); s += e[j]; }
        float logs = __logf(s);
        float invs = 1.0f / s;

        const float4* G1 = (const float4*)&g1[(size_t)grow * C_DIM + gcol];
        const float4* G2 = (const float4*)&g2[(size_t)grow * C_DIM + gcol];
        int i1 = 0, i2 = 0;
        float bv1 = -INFINITY, bv2 = -INFINITY;
        float bv1b = -INFINITY, bv2b = -INFINITY;
#define UPD1(val, idx) { float v = lp + (val); if (v > bv1) { bv1b = bv1; bv1 = v; i1 = (idx); } else if (v > bv1b) bv1b = v; }
#define UPD2(val, idx) { float u = lp + (val); if (u > bv2) { bv2b = bv2; bv2 = u; i2 = (idx); } else if (u > bv2b) bv2b = u; }
#pragma unroll
        for (int q = 0; q < 8; q++) {
            float4 a = G1[q];
            float4 b = G2[q];
            float lp;
            lp = (L[q * 4 + 0] - m) - logs; UPD1(a.x, q * 4 + 0) UPD2(b.x, q * 4 + 0)
            lp = (L[q * 4 + 1] - m) - logs; UPD1(a.y, q * 4 + 1) UPD2(b.y, q * 4 + 1)
            lp = (L[q * 4 + 2] - m) - logs; UPD1(a.z, q * 4 + 2) UPD2(b.z, q * 4 + 2)
            lp = (L[q * 4 + 3] - m) - logs; UPD1(a.w, q * 4 + 3) UPD2(b.w, q * 4 + 3)
        }
#undef UPD1
#undef UPD2

        float soft_i1 = e[i1] * invs;
        float soft_i2 = e[i2] * invs;

        float uu = uin[grow * G_NUM + ggrp];
        float ww = wint[grow * G_NUM + ggrp];
        float v1 = (uu < 1.0f) ? ww : 1.0f;
        float v2 = (uu < 1.0f) ? (1.0f - ww) : 0.0f;
        float c1, c2;
        if (i1 == i2) { c1 = soft_i1 + ((v1 + v2) - soft_i1); c2 = 0.0f; }
        else          { c1 = soft_i1 + (v1 - soft_i1); c2 = soft_i2 + (v2 - soft_i2); }

        // record sampling result (dense materialization happens in copy-out)
        idx_s[row * 4 + gg] = i1 | (i2 << 8);
        cf2_s[(row * 4 + gg) * 2 + 0] = c1;
        cf2_s[(row * 4 + gg) * 2 + 1] = c2;

#pragma unroll
        for (int j = 0; j < 32; j++) Lp[j] = e[j] * invs;

        int slot = grow * G_NUM + ggrp;
        g_idx[slot] = i1 | (i2 << 8);
        g_coef[2 * slot + 0] = c1;
        g_coef[2 * slot + 1] = c2;

        // flag near-tie groups for exact sequential-fp32 recompute
        if (fminf(bv1 - bv1b, bv2 - bv2b) < TAU) {
            int fp = atomicAdd(&g_nfix, 1);
            if (fp < MAXFIX) g_fixlist[fp] = slot;
        }
    }
    __syncthreads();

    // -------- coalesced copy-out: soft from smem; sampled reconstructed from idx/coef --------
#pragma unroll
    for (int v = 0; v < 16; v++) {
        int u = v * 256 + tid;
        int row = u >> 5, q = u & 31;
        float4 sv;
        sv.x = Ls[row * LSTR + q * 4 + 0];
        sv.y = Ls[row * LSTR + q * 4 + 1];
        sv.z = Ls[row * LSTR + q * 4 + 2];
        sv.w = Ls[row * LSTR + q * 4 + 3];
        *(float4*)&out_soft[(size_t)(row0 + row) * C_DIM + col0 + q * 4] = sv;

        int gg = q >> 3;
        int pk = idx_s[row * 4 + gg];
        int i1 = pk & 255, i2 = (pk >> 8) & 255;
        float c1 = cf2_s[(row * 4 + gg) * 2 + 0];
        float c2 = cf2_s[(row * 4 + gg) * 2 + 1];
        int j0 = (q & 7) * 4;
        float4 sp;
        sp.x = ((j0 + 0 == i1) ? c1 : 0.0f) + ((j0 + 0 == i2) ? c2 : 0.0f);
        sp.y = ((j0 + 1 == i1) ? c1 : 0.0f) + ((j0 + 1 == i2) ? c2 : 0.0f);
        sp.z = ((j0 + 2 == i1) ? c1 : 0.0f) + ((j0 + 2 == i2) ? c2 : 0.0f);
        sp.w = ((j0 + 3 == i1) ? c1 : 0.0f) + ((j0 + 3 == i2) ? c2 : 0.0f);
        *(float4*)&out_sampled[(size_t)(row0 + row) * C_DIM + col0 + q * 4] = sp;
    }
}

// ---------------- K1b: exact sequential-fp32 recompute of flagged groups ----------------
#define WROWS 513
#define FIXSMEM ((512 + 32 * WROWS + 32) * 4)   // 67840
#define FIXGRID 2048

__global__ __launch_bounds__(256)
void k1b_fix(const float* __restrict__ x, const float* __restrict__ W1,
             const float* __restrict__ b1, const float* __restrict__ coff,
             const float* __restrict__ g1, const float* __restrict__ g2,
             const float* __restrict__ wint, const float* __restrict__ uin,
             float* __restrict__ out_sampled, float* __restrict__ out_soft) {
    extern __shared__ float fs[];
    float* xsh = fs;                    // [512]
    float* wsh = fs + 512;              // [32][513]
    float* sL  = fs + 512 + 32 * WROWS; // [32]

    int n = g_nfix;
    if (n > MAXFIX) n = MAXFIX;
    const int tid = threadIdx.x;

    for (int bi = blockIdx.x; bi < n; bi += FIXGRID) {
        __syncthreads();   // protect smem reuse across iterations
        const int slot = g_fixlist[bi];
        const int row  = slot >> 5;
        const int ggrp = slot & 31;
        const int gcol = ggrp * 32;

        for (int i = tid; i < 512 / 4; i += 256) {
            float4 v = *(const float4*)&x[(size_t)row * E_DIM + i * 4];
            xsh[i * 4 + 0] = v.x; xsh[i * 4 + 1] = v.y;
            xsh[i * 4 + 2] = v.z; xsh[i * 4 + 3] = v.w;
        }
        for (int u = tid; u < 32 * 128; u += 256) {
            int j = u >> 7, kq = u & 127;
            float4 v = *(const float4*)&W1[(size_t)(gcol + j) * E_DIM + kq * 4];
            wsh[j * WROWS + kq * 4 + 0] = v.x;
            wsh[j * WROWS + kq * 4 + 1] = v.y;
            wsh[j * WROWS + kq * 4 + 2] = v.z;
            wsh[j * WROWS + kq * 4 + 3] = v.w;
        }
        __syncthreads();

        if (tid < 32) {
            // exact sequential fp32 FMA chain, k = 0..511 (bitwise == the R6 path)
            const float* wr = wsh + tid * WROWS;
            float acc = 0.0f;
            for (int k = 0; k < 512; k++) acc = __fmaf_rn(xsh[k], wr[k], acc);
            sL[tid] = (acc + b1[gcol + tid]) * 3.0f + coff[gcol + tid];
        }
        __syncthreads();

        if (tid == 0) {
            float L[32];
#pragma unroll
            for (int j = 0; j < 32; j++) L[j] = sL[j];
            float m = -INFINITY;
#pragma unroll
            for (int j = 0; j < 32; j++) m = fmaxf(m, L[j]);
            float e[32];
            float s = 0.0f;
#pragma unroll
            for (int j = 0; j < 32; j++) { e[j] = __expf(L[j] - m); s += e[j]; }
            float logs = __logf(s);
            float invs = 1.0f / s;

            const float* G1 = &g1[(size_t)row * C_DIM + gcol];
            const float* G2 = &g2[(size_t)row * C_DIM + gcol];
            int i1 = 0, i2 = 0;
            float bv1 = -INFINITY, bv2 = -INFINITY;
#pragma unroll
            for (int j = 0; j < 32; j++) {
                float lp = (L[j] - m) - logs;
                float v = lp + G1[j]; if (v > bv1) { bv1 = v; i1 = j; }
                float u = lp + G2[j]; if (u > bv2) { bv2 = u; i2 = j; }
            }

            float soft_i1 = e[i1] * invs;
            float soft_i2 = e[i2] * invs;
            float uu = uin[row * G_NUM + ggrp];
            float ww = wint[row * G_NUM + ggrp];
            float v1 = (uu < 1.0f) ? ww : 1.0f;
            float v2 = (uu < 1.0f) ? (1.0f - ww) : 0.0f;
            float c1, c2;
            if (i1 == i2) { c1 = soft_i1 + ((v1 + v2) - soft_i1); c2 = 0.0f; }
            else          { c1 = soft_i1 + (v1 - soft_i1); c2 = soft_i2 + (v2 - soft_i2); }

#pragma unroll
            for (int j = 0; j < 32; j++) {
                out_soft[(size_t)row * C_DIM + gcol + j] = e[j] * invs;
                out_sampled[(size_t)row * C_DIM + gcol + j] =
                    ((j == i1) ? c1 : 0.0f) + ((j == i2 && i2 != i1) ? c2 : 0.0f);
            }
            g_idx[slot] = i1 | (i2 << 8);
            g_coef[2 * slot + 0] = c1;
            g_coef[2 * slot + 1] = c2;
        }
    }
}

// ---------------- K2: sparse projection (direct L1 gather) + LayerNorm ----------------
__global__ __launch_bounds__(512)
void k_proj_ln(const float* __restrict__ b2, const float* __restrict__ gamma,
               const float* __restrict__ beta,
               float* __restrict__ out_pos, float* __restrict__ out_neg) {
    const int tid = threadIdx.x;
    const int lane = tid & 31;
    const int wid  = tid >> 5;
    const int rowbase = blockIdx.x * 64;

    float4 h[4][4];
#pragma unroll
    for (int q = 0; q < 4; q++)
#pragma unroll
        for (int k = 0; k < 4; k++) h[q][k] = make_float4(0.f, 0.f, 0.f, 0.f);

#pragma unroll 1
    for (int g = 0; g < G_NUM; g++) {
#pragma unroll
        for (int q = 0; q < 4; q++) {
            int grow = rowbase + wid * 4 + q;
            int slot = grow * G_NUM + g;
            int packed = g_idx[slot];
            int i1 = packed & 255;
            int i2 = (packed >> 8) & 255;
            float c1 = g_coef[2 * slot + 0];
            float c2 = g_coef[2 * slot + 1];
            const float4* s1 = (const float4*)&g_W2T[(size_t)(g * CG_NUM + i1) * E_DIM];
            const float4* s2 = (const float4*)&g_W2T[(size_t)(g * CG_NUM + i2) * E_DIM];
#pragma unroll
            for (int k = 0; k < 4; k++) {
                float4 a = __ldg(&s1[lane + 32 * k]);
                float4 b = __ldg(&s2[lane + 32 * k]);
                h[q][k].x = fmaf(c1, a.x, fmaf(c2, b.x, h[q][k].x));
                h[q][k].y = fmaf(c1, a.y, fmaf(c2, b.y, h[q][k].y));
                h[q][k].z = fmaf(c1, a.z, fmaf(c2, b.z, h[q][k].z));
                h[q][k].w = fmaf(c1, a.w, fmaf(c2, b.w, h[q][k].w));
            }
        }
    }

    float4 b2r[4], gr[4], br[4];
#pragma unroll
    for (int k = 0; k < 4; k++) {
        b2r[k] = *(const float4*)&b2[lane * 4 + 128 * k];
        gr[k]  = *(const float4*)&gamma[lane * 4 + 128 * k];
        br[k]  = *(const float4*)&beta[lane * 4 + 128 * k];
    }

#pragma unroll
    for (int q = 0; q < 4; q++) {
        int grow = rowbase + wid * 4 + q;
        float sum = 0.0f;
#pragma unroll
        for (int k = 0; k < 4; k++) {
            h[q][k].x += b2r[k].x; h[q][k].y += b2r[k].y;
            h[q][k].z += b2r[k].z; h[q][k].w += b2r[k].w;
            sum += h[q][k].x + h[q][k].y + h[q][k].z + h[q][k].w;
        }
#pragma unroll
        for (int o = 16; o > 0; o >>= 1) sum += __shfl_xor_sync(0xffffffffu, sum, o);
        float mu = sum * (1.0f / 512.0f);
        float vs = 0.0f;
#pragma unroll
        for (int k = 0; k < 4; k++) {
            float dx;
            dx = h[q][k].x - mu; vs += dx * dx;
            dx = h[q][k].y - mu; vs += dx * dx;
            dx = h[q][k].z - mu; vs += dx * dx;
            dx = h[q][k].w - mu; vs += dx * dx;
        }
#pragma unroll
        for (int o = 16; o > 0; o >>= 1) vs += __shfl_xor_sync(0xffffffffu, vs, o);
        float var = vs * (1.0f / 512.0f);
        float sc = rsqrtf(var + 1e-5f);
#pragma unroll
        for (int k = 0; k < 4; k++) {
            float4 o4;
            o4.x = (h[q][k].x - mu) * sc * gr[k].x + br[k].x;
            o4.y = (h[q][k].y - mu) * sc * gr[k].y + br[k].y;
            o4.z = (h[q][k].z - mu) * sc * gr[k].z + br[k].z;
            o4.w = (h[q][k].w - mu) * sc * gr[k].w + br[k].w;
            int off = grow * E_DIM + lane * 4 + 128 * k;
            *(float4*)&out_pos[off] = o4;
            *(float4*)&out_neg[off] = o4;
        }
    }
}

extern "C" void kernel_launch(void* const* d_in, const int* in_sizes, int n_in,
                              void* d_out, int out_size) {
    const float* x     = (const float*)d_in[0];
    const float* W1    = (const float*)d_in[1];
    const float* b1    = (const float*)d_in[2];
    const float* coff  = (const float*)d_in[3];
    const float* W2    = (const float*)d_in[4];
    const float* b2    = (const float*)d_in[5];
    const float* gamma = (const float*)d_in[6];
    const float* beta  = (const float*)d_in[7];
    const float* g1    = (const float*)d_in[8];
    const float* g2    = (const float*)d_in[9];
    const float* wi    = (const float*)d_in[10];
    const float* ui    = (const float*)d_in[11];

    float* out = (float*)d_out;
    float* out_sampled = out;
    float* out_soft    = out + (size_t)SN * C_DIM;
    float* out_pos     = out + (size_t)2 * SN * C_DIM;
    float* out_neg     = out_pos + (size_t)SN * E_DIM;

    k_split_x<<<SN * E_DIM / 1024, 256>>>(x);
    k_split_w<<<C_DIM * E_DIM / 1024, 256>>>(W1);
    k_transpose<<<dim3(32, 16), dim3(32, 8)>>>(W2);

    cudaFuncSetAttribute(k1_mma, cudaFuncAttributeMaxDynamicSharedMemorySize, SMEM_K1);
    k1_mma<<<dim3(C_DIM / BN, SN / BM), 256, SMEM_K1>>>(
        b1, coff, g1, g2, wi, ui, out_sampled, out_soft);

    cudaFuncSetAttribute(k1b_fix, cudaFuncAttributeMaxDynamicSharedMemorySize, FIXSMEM);
    k1b_fix<<<FIXGRID, 256, FIXSMEM>>>(x, W1, b1, coff, g1, g2, wi, ui,
                                       out_sampled, out_soft);

    cudaFuncSetAttribute(k_proj_ln, cudaFuncAttributePreferredSharedMemoryCarveout, 0);
    k_proj_ln<<<SN / 64, 512>>>(b2, gamma, beta, out_pos, out_neg);
}

// round 16
// speedup vs baseline: 1.7093x; 1.0109x over previous
#include <cuda_runtime.h>
#include <cuda_bf16.h>
#include <math.h>
#include <stdint.h>

#define SN     16384
#define E_DIM  512
#define C_DIM  1024
#define G_NUM  32
#define CG_NUM 32
#define MAXFIX 16384
#define TAU    1e-3f

// ---------------- scratch (static device globals: no runtime allocation) ----------------
__device__ __align__(16) __nv_bfloat16 g_xh[SN * E_DIM];
__device__ __align__(16) __nv_bfloat16 g_xl[SN * E_DIM];
__device__ __align__(16) __nv_bfloat16 g_wh[C_DIM * E_DIM];
__device__ __align__(16) __nv_bfloat16 g_wl[C_DIM * E_DIM];
__device__ float g_W2T[C_DIM * E_DIM];   // W2 transposed to (C, E)
__device__ int   g_idx[SN * G_NUM];      // packed argmax indices
__device__ float g_coef[SN * G_NUM * 2]; // straight-through coefficients
__device__ int   g_nfix;
__device__ int   g_fixlist[MAXFIX];

// ---------------- helpers ----------------
static __device__ __forceinline__ uint32_t smem_u32(const void* p) {
    uint32_t a;
    asm("{ .reg .u64 t; cvta.to.shared.u64 t, %1; cvt.u32.u64 %0, t; }" : "=r"(a) : "l"(p));
    return a;
}
static __device__ __forceinline__ void ldsm_x4(uint32_t* r, uint32_t addr) {
    asm volatile("ldmatrix.sync.aligned.m8n8.x4.shared.b16 {%0,%1,%2,%3}, [%4];"
        : "=r"(r[0]), "=r"(r[1]), "=r"(r[2]), "=r"(r[3]) : "r"(addr));
}
static __device__ __forceinline__ void mma_bf16(float* d, const uint32_t* a, const uint32_t* b) {
    asm volatile("mma.sync.aligned.m16n8k16.row.col.f32.bf16.bf16.f32 "
        "{%0,%1,%2,%3}, {%4,%5,%6,%7}, {%8,%9}, {%0,%1,%2,%3};"
        : "+f"(d[0]), "+f"(d[1]), "+f"(d[2]), "+f"(d[3])
        : "r"(a[0]), "r"(a[1]), "r"(a[2]), "r"(a[3]), "r"(b[0]), "r"(b[1]));
}
static __device__ __forceinline__ void cp16(uint32_t dst, const void* src) {
    asm volatile("cp.async.cg.shared.global [%0], [%1], 16;" :: "r"(dst), "l"(src));
}

// ---------------- fused split: fp32 -> bf16 double split for x AND W1 ----------------
static __device__ __forceinline__ void split2(float x, __nv_bfloat16& a, __nv_bfloat16& b) {
    a = __float2bfloat16_rn(x);
    b = __float2bfloat16_rn(x - __bfloat162float(a));
}
__global__ void k_split(const float* __restrict__ x, const float* __restrict__ W1) {
    if (blockIdx.x == 0 && threadIdx.x == 0) g_nfix = 0;   // fused reset
    size_t i = ((size_t)blockIdx.x * 256 + threadIdx.x) * 4;
    const size_t XN = (size_t)SN * E_DIM;
    const bool isw = (i >= XN);
    const float* src = isw ? (W1 + (i - XN)) : (x + i);
    __nv_bfloat16* dh = isw ? (g_wh + (i - XN)) : (g_xh + i);
    __nv_bfloat16* dl = isw ? (g_wl + (i - XN)) : (g_xl + i);
    float4 v = *(const float4*)src;
    __nv_bfloat16 h[4], l[4];
    split2(v.x, h[0], l[0]); split2(v.y, h[1], l[1]);
    split2(v.z, h[2], l[2]); split2(v.w, h[3], l[3]);
    ((__nv_bfloat162*)dh)[0] = __nv_bfloat162(h[0], h[1]);
    ((__nv_bfloat162*)dh)[1] = __nv_bfloat162(h[2], h[3]);
    ((__nv_bfloat162*)dl)[0] = __nv_bfloat162(l[0], l[1]);
    ((__nv_bfloat162*)dl)[1] = __nv_bfloat162(l[2], l[3]);
}

// ---------------- K0: transpose W2 (E, C) -> g_W2T (C, E) ----------------
__global__ void k_transpose(const float* __restrict__ W2) {
    __shared__ float tile[32][33];
    const int bx = blockIdx.x, by = blockIdx.y;
    const int tx = threadIdx.x, ty = threadIdx.y;
#pragma unroll
    for (int j = 0; j < 4; j++)
        tile[ty + j * 8][tx] = W2[(by * 32 + ty + j * 8) * C_DIM + bx * 32 + tx];
    __syncthreads();
#pragma unroll
    for (int j = 0; j < 4; j++)
        g_W2T[(bx * 32 + ty + j * 8) * E_DIM + by * 32 + tx] = tile[tx][ty + j * 8];
}

// ---------------- K1a: warp-HMMA bf16x2 (3-product) GEMM, 2 CTAs/SM ----------------
#define BM 128
#define BN 128
#define KC 32
#define NCHUNK (E_DIM / KC)        // 16
#define AROW 80
#define ABUF (128 * AROW)          // 10240
#define BBUF (128 * AROW)          // 10240
#define BUFB (2 * ABUF + 2 * BBUF) // 40960 per stage
#define LSTR 131
#define SM_BIAS (2 * BUFB)         // 81920 (stages 81920 ∪ logits 67072)
#define SM_COF  (SM_BIAS + 512)
#define SM_IDX  (SM_COF + 512)     // int[128*4] = 2048
#define SM_CF2  (SM_IDX + 2048)    // float[128*4*2] = 4096
#define SMEM_K1 (SM_CF2 + 4096)    // 89088

__global__ __launch_bounds__(256, 2)
void k1_mma(const float* __restrict__ b1, const float* __restrict__ coff,
            const float* __restrict__ g1, const float* __restrict__ g2,
            const float* __restrict__ wint, const float* __restrict__ uin,
            float* __restrict__ out_sampled, float* __restrict__ out_soft) {
    extern __shared__ char smem[];
    const uint32_t sb = smem_u32(smem);
    const int tid = threadIdx.x;
    const int lane = tid & 31;
    const int wid = tid >> 5;              // 8 warps: wm = wid>>1 (0..3), wn = wid&1
    const int wm = wid >> 1, wn = wid & 1;
    const int row0 = blockIdx.y * BM;
    const int col0 = blockIdx.x * BN;
    float* b1s = (float*)(smem + SM_BIAS);
    float* cfs = (float*)(smem + SM_COF);
    int*   idx_s = (int*)(smem + SM_IDX);
    float* cf2_s = (float*)(smem + SM_CF2);

    if (tid < 128) { b1s[tid] = b1[col0 + tid]; cfs[tid] = coff[col0 + tid]; }

    float acc[2][8][4];
#pragma unroll
    for (int mt = 0; mt < 2; mt++)
#pragma unroll
        for (int nt = 0; nt < 8; nt++)
#pragma unroll
            for (int k = 0; k < 4; k++) acc[mt][nt][k] = 0.0f;

    const __nv_bfloat16* xs[2] = { g_xh, g_xl };
    const __nv_bfloat16* ws[2] = { g_wh, g_wl };

    auto load_chunk = [&](int c, int b) {
        const int kk = c * KC;
#pragma unroll
        for (int p = 0; p < 4; p++) {          // A: 2 splits x 128 rows x 4 x16B
            int u = p * 256 + tid;
            int split = u >> 9;
            int rem = u & 511;
            int row = rem >> 2, c16 = rem & 3;
            cp16(sb + b * BUFB + split * ABUF + row * AROW + c16 * 16,
                 xs[split] + (size_t)(row0 + row) * E_DIM + kk + c16 * 8);
        }
#pragma unroll
        for (int p = 0; p < 4; p++) {          // B: 2 splits x 128 rows x 4 x16B
            int u = p * 256 + tid;
            int split = u >> 9;
            int rem = u & 511;
            int row = rem >> 2, c16 = rem & 3;
            cp16(sb + b * BUFB + 2 * ABUF + split * BBUF + row * AROW + c16 * 16,
                 ws[split] + (size_t)(col0 + row) * E_DIM + kk + c16 * 8);
        }
        asm volatile("cp.async.commit_group;" ::: "memory");
    };

    load_chunk(0, 0);
    for (int c = 0; c < NCHUNK; c++) {
        const int b = c & 1;
        if (c + 1 < NCHUNK) {
            load_chunk(c + 1, b ^ 1);
            asm volatile("cp.async.wait_group 1;" ::: "memory");
        } else {
            asm volatile("cp.async.wait_group 0;" ::: "memory");
        }
        __syncthreads();

        const int r = lane & 7, blk = lane >> 3;
        const int am_off = (blk & 1) * 8 + r;
        const int ak_off = (blk >> 1) * 8;
        const int bn_off = (blk >> 1) * 8 + r;
        const int bk_off = (blk & 1) * 8;
#pragma unroll
        for (int kss = 0; kss < 2; kss++) {
            uint32_t afr[2][2][4];
#pragma unroll
            for (int s = 0; s < 2; s++)
#pragma unroll
                for (int mt = 0; mt < 2; mt++)
                    ldsm_x4(afr[s][mt], sb + b * BUFB + s * ABUF
                            + (wm * 32 + mt * 16 + am_off) * AROW + (kss * 16 + ak_off) * 2);
#pragma unroll
            for (int np = 0; np < 4; np++) {
                uint32_t bfr[2][4];
#pragma unroll
                for (int s = 0; s < 2; s++)
                    ldsm_x4(bfr[s], sb + b * BUFB + 2 * ABUF + s * BBUF
                            + (wn * 64 + np * 16 + bn_off) * AROW + (kss * 16 + bk_off) * 2);
#pragma unroll
                for (int mt = 0; mt < 2; mt++)
#pragma unroll
                    for (int nt = 0; nt < 2; nt++) {
                        float* ac = acc[mt][np * 2 + nt];
                        mma_bf16(ac, afr[0][mt], &bfr[0][nt * 2]);   // hh
                        mma_bf16(ac, afr[0][mt], &bfr[1][nt * 2]);   // hl
                        mma_bf16(ac, afr[1][mt], &bfr[0][nt * 2]);   // lh
                    }
            }
        }
        __syncthreads();
    }

    // -------- logits (reference order) to smem --------
    float* Ls = (float*)smem;
    const int r0l = lane >> 2, c0l = (lane & 3) * 2;
#pragma unroll
    for (int mt = 0; mt < 2; mt++)
#pragma unroll
        for (int nt = 0; nt < 8; nt++) {
            int row = wm * 32 + mt * 16 + r0l;
            int col = wn * 64 + nt * 8 + c0l;
            Ls[row * LSTR + col]           = (acc[mt][nt][0] + b1s[col])     * 3.0f + cfs[col];
            Ls[row * LSTR + col + 1]       = (acc[mt][nt][1] + b1s[col + 1]) * 3.0f + cfs[col + 1];
            Ls[(row + 8) * LSTR + col]     = (acc[mt][nt][2] + b1s[col])     * 3.0f + cfs[col];
            Ls[(row + 8) * LSTR + col + 1] = (acc[mt][nt][3] + b1s[col + 1]) * 3.0f + cfs[col + 1];
        }
    __syncthreads();

    // -------- per-(row, group) softmax + Gumbel sampling + gap flagging --------
#pragma unroll 1
    for (int p = 0; p < 2; p++) {
        const int task = p * 256 + tid;
        const int row = task & 127;
        const int gg  = task >> 7;             // 0..3
        const int grow = row0 + row;
        const int gcol = col0 + gg * CG_NUM;
        const int ggrp = gcol >> 5;
        float* Lp = &Ls[row * LSTR + gg * CG_NUM];

        float L[32];
#pragma unroll
        for (int j = 0; j < 32; j++) L[j] = Lp[j];

        float m = -INFINITY;
#pragma unroll
        for (int j = 0; j < 32; j++) m = fmaxf(m, L[j]);
        float e[32];
        float s = 0.0f;
#pragma unroll
        for (int j = 0; j < 32; j++) { e[j] = __expf(L[j] - m); s += e[j]; }
        float logs = __logf(s);
        float invs = 1.0f / s;

        const float4* G1 = (const float4*)&g1[(size_t)grow * C_DIM + gcol];
        const float4* G2 = (const float4*)&g2[(size_t)grow * C_DIM + gcol];
        int i1 = 0, i2 = 0;
        float bv1 = -INFINITY, bv2 = -INFINITY;
        float bv1b = -INFINITY, bv2b = -INFINITY;
#define UPD1(val, idx) { float v = lp + (val); if (v > bv1) { bv1b = bv1; bv1 = v; i1 = (idx); } else if (v > bv1b) bv1b = v; }
#define UPD2(val, idx) { float u = lp + (val); if (u > bv2) { bv2b = bv2; bv2 = u; i2 = (idx); } else if (u > bv2b) bv2b = u; }
#pragma unroll
        for (int q = 0; q < 8; q++) {
            float4 a = G1[q];
            float4 b = G2[q];
            float lp;
            lp = (L[q * 4 + 0] - m) - logs; UPD1(a.x, q * 4 + 0) UPD2(b.x, q * 4 + 0)
            lp = (L[q * 4 + 1] - m) - logs; UPD1(a.y, q * 4 + 1) UPD2(b.y, q * 4 + 1)
            lp = (L[q * 4 + 2] - m) - logs; UPD1(a.z, q * 4 + 2) UPD2(b.z, q * 4 + 2)
            lp = (L[q * 4 + 3] - m) - logs; UPD1(a.w, q * 4 + 3) UPD2(b.w, q * 4 + 3)
        }
#undef UPD1
#undef UPD2

        float soft_i1 = e[i1] * invs;
        float soft_i2 = e[i2] * invs;

        float uu = uin[grow * G_NUM + ggrp];
        float ww = wint[grow * G_NUM + ggrp];
        float v1 = (uu < 1.0f) ? ww : 1.0f;
        float v2 = (uu < 1.0f) ? (1.0f - ww) : 0.0f;
        float c1, c2;
        if (i1 == i2) { c1 = soft_i1 + ((v1 + v2) - soft_i1); c2 = 0.0f; }
        else          { c1 = soft_i1 + (v1 - soft_i1); c2 = soft_i2 + (v2 - soft_i2); }

        // record sampling result (dense materialization happens in copy-out)
        idx_s[row * 4 + gg] = i1 | (i2 << 8);
        cf2_s[(row * 4 + gg) * 2 + 0] = c1;
        cf2_s[(row * 4 + gg) * 2 + 1] = c2;

#pragma unroll
        for (int j = 0; j < 32; j++) Lp[j] = e[j] * invs;

        int slot = grow * G_NUM + ggrp;
        g_idx[slot] = i1 | (i2 << 8);
        g_coef[2 * slot + 0] = c1;
        g_coef[2 * slot + 1] = c2;

        // flag near-tie groups for exact sequential-fp32 recompute
        if (fminf(bv1 - bv1b, bv2 - bv2b) < TAU) {
            int fp = atomicAdd(&g_nfix, 1);
            if (fp < MAXFIX) g_fixlist[fp] = slot;
        }
    }
    __syncthreads();

    // -------- coalesced copy-out: soft from smem; sampled reconstructed from idx/coef --------
#pragma unroll
    for (int v = 0; v < 16; v++) {
        int u = v * 256 + tid;
        int row = u >> 5, q = u & 31;
        float4 sv;
        sv.x = Ls[row * LSTR + q * 4 + 0];
        sv.y = Ls[row * LSTR + q * 4 + 1];
        sv.z = Ls[row * LSTR + q * 4 + 2];
        sv.w = Ls[row * LSTR + q * 4 + 3];
        *(float4*)&out_soft[(size_t)(row0 + row) * C_DIM + col0 + q * 4] = sv;

        int gg = q >> 3;
        int pk = idx_s[row * 4 + gg];
        int i1 = pk & 255, i2 = (pk >> 8) & 255;
        float c1 = cf2_s[(row * 4 + gg) * 2 + 0];
        float c2 = cf2_s[(row * 4 + gg) * 2 + 1];
        int j0 = (q & 7) * 4;
        float4 sp;
        sp.x = ((j0 + 0 == i1) ? c1 : 0.0f) + ((j0 + 0 == i2) ? c2 : 0.0f);
        sp.y = ((j0 + 1 == i1) ? c1 : 0.0f) + ((j0 + 1 == i2) ? c2 : 0.0f);
        sp.z = ((j0 + 2 == i1) ? c1 : 0.0f) + ((j0 + 2 == i2) ? c2 : 0.0f);
        sp.w = ((j0 + 3 == i1) ? c1 : 0.0f) + ((j0 + 3 == i2) ? c2 : 0.0f);
        *(float4*)&out_sampled[(size_t)(row0 + row) * C_DIM + col0 + q * 4] = sp;
    }
}

// ---------------- K1b: warp-per-slot exact sequential-fp32 recompute ----------------
#define FIXBLOCKS 256

__global__ __launch_bounds__(256)
void k1b_fix(const float* __restrict__ x, const float* __restrict__ W1,
             const float* __restrict__ b1, const float* __restrict__ coff,
             const float* __restrict__ g1, const float* __restrict__ g2,
             const float* __restrict__ wint, const float* __restrict__ uin,
             float* __restrict__ out_sampled, float* __restrict__ out_soft) {
    int n = g_nfix;
    if (n > MAXFIX) n = MAXFIX;
    const int lane = threadIdx.x & 31;
    const int wwid = threadIdx.x >> 5;     // 8 warps per block
    const unsigned FULL = 0xffffffffu;

    for (int bi = blockIdx.x * 8 + wwid; bi < n; bi += FIXBLOCKS * 8) {
        const int slot = g_fixlist[bi];
        const int row  = slot >> 5;
        const int ggrp = slot & 31;
        const int gcol = ggrp * 32;

        // lane = class j; exact sequential fp32 FMA chain k = 0..511 (bitwise == R6 path)
        const float4* xr = (const float4*)&x[(size_t)row * E_DIM];
        const float4* wr = (const float4*)&W1[(size_t)(gcol + lane) * E_DIM];
        float acc = 0.0f;
#pragma unroll 8
        for (int k = 0; k < 128; k++) {
            float4 xv = __ldg(&xr[k]);
            float4 wv = __ldg(&wr[k]);
            acc = __fmaf_rn(xv.x, wv.x, acc);
            acc = __fmaf_rn(xv.y, wv.y, acc);
            acc = __fmaf_rn(xv.z, wv.z, acc);
            acc = __fmaf_rn(xv.w, wv.w, acc);
        }
        float L = (acc + b1[gcol + lane]) * 3.0f + coff[gcol + lane];

        // warp max (order-independent) and sum (feeds only uniform shift + soft values)
        float m = L;
#pragma unroll
        for (int o = 16; o > 0; o >>= 1) m = fmaxf(m, __shfl_xor_sync(FULL, m, o));
        float e = __expf(L - m);
        float s = e;
#pragma unroll
        for (int o = 16; o > 0; o >>= 1) s += __shfl_xor_sync(FULL, s, o);
        float logs = __logf(s);
        float invs = 1.0f / s;
        float lp = (L - m) - logs;

        float a1 = lp + __ldg(&g1[(size_t)row * C_DIM + gcol + lane]);
        float a2 = lp + __ldg(&g2[(size_t)row * C_DIM + gcol + lane]);

        // warp argmax with first-index tie rule (matches jnp.argmax)
        float bv1 = a1; int i1 = lane;
        float bv2 = a2; int i2 = lane;
#pragma unroll
        for (int o = 16; o > 0; o >>= 1) {
            float ov = __shfl_xor_sync(FULL, bv1, o);
            int   oi = __shfl_xor_sync(FULL, i1, o);
            if (ov > bv1 || (ov == bv1 && oi < i1)) { bv1 = ov; i1 = oi; }
            ov = __shfl_xor_sync(FULL, bv2, o);
            oi = __shfl_xor_sync(FULL, i2, o);
            if (ov > bv2 || (ov == bv2 && oi < i2)) { bv2 = ov; i2 = oi; }
        }

        float soft_lane = e * invs;
        float soft_i1 = __shfl_sync(FULL, soft_lane, i1);
        float soft_i2 = __shfl_sync(FULL, soft_lane, i2);

        float uu = uin[row * G_NUM + ggrp];
        float ww = wint[row * G_NUM + ggrp];
        float v1 = (uu < 1.0f) ? ww : 1.0f;
        float v2 = (uu < 1.0f) ? (1.0f - ww) : 0.0f;
        float c1, c2;
        if (i1 == i2) { c1 = soft_i1 + ((v1 + v2) - soft_i1); c2 = 0.0f; }
        else          { c1 = soft_i1 + (v1 - soft_i1); c2 = soft_i2 + (v2 - soft_i2); }

        out_soft[(size_t)row * C_DIM + gcol + lane] = soft_lane;
        out_sampled[(size_t)row * C_DIM + gcol + lane] =
            ((lane == i1) ? c1 : 0.0f) + ((lane == i2 && i2 != i1) ? c2 : 0.0f);

        if (lane == 0) {
            g_idx[slot] = i1 | (i2 << 8);
            g_coef[2 * slot + 0] = c1;
            g_coef[2 * slot + 1] = c2;
        }
    }
}

// ---------------- K2: sparse projection (direct L1 gather) + LayerNorm ----------------
__global__ __launch_bounds__(512)
void k_proj_ln(const float* __restrict__ b2, const float* __restrict__ gamma,
               const float* __restrict__ beta,
               float* __restrict__ out_pos, float* __restrict__ out_neg) {
    const int tid = threadIdx.x;
    const int lane = tid & 31;
    const int wid  = tid >> 5;
    const int rowbase = blockIdx.x * 64;

    float4 h[4][4];
#pragma unroll
    for (int q = 0; q < 4; q++)
#pragma unroll
        for (int k = 0; k < 4; k++) h[q][k] = make_float4(0.f, 0.f, 0.f, 0.f);

#pragma unroll 1
    for (int g = 0; g < G_NUM; g++) {
#pragma unroll
        for (int q = 0; q < 4; q++) {
            int grow = rowbase + wid * 4 + q;
            int slot = grow * G_NUM + g;
            int packed = g_idx[slot];
            int i1 = packed & 255;
            int i2 = (packed >> 8) & 255;
            float c1 = g_coef[2 * slot + 0];
            float c2 = g_coef[2 * slot + 1];
            const float4* s1 = (const float4*)&g_W2T[(size_t)(g * CG_NUM + i1) * E_DIM];
            const float4* s2 = (const float4*)&g_W2T[(size_t)(g * CG_NUM + i2) * E_DIM];
#pragma unroll
            for (int k = 0; k < 4; k++) {
                float4 a = __ldg(&s1[lane + 32 * k]);
                float4 b = __ldg(&s2[lane + 32 * k]);
                h[q][k].x = fmaf(c1, a.x, fmaf(c2, b.x, h[q][k].x));
                h[q][k].y = fmaf(c1, a.y, fmaf(c2, b.y, h[q][k].y));
                h[q][k].z = fmaf(c1, a.z, fmaf(c2, b.z, h[q][k].z));
                h[q][k].w = fmaf(c1, a.w, fmaf(c2, b.w, h[q][k].w));
            }
        }
    }

    float4 b2r[4], gr[4], br[4];
#pragma unroll
    for (int k = 0; k < 4; k++) {
        b2r[k] = *(const float4*)&b2[lane * 4 + 128 * k];
        gr[k]  = *(const float4*)&gamma[lane * 4 + 128 * k];
        br[k]  = *(const float4*)&beta[lane * 4 + 128 * k];
    }

#pragma unroll
    for (int q = 0; q < 4; q++) {
        int grow = rowbase + wid * 4 + q;
        float sum = 0.0f;
#pragma unroll
        for (int k = 0; k < 4; k++) {
            h[q][k].x += b2r[k].x; h[q][k].y += b2r[k].y;
            h[q][k].z += b2r[k].z; h[q][k].w += b2r[k].w;
            sum += h[q][k].x + h[q][k].y + h[q][k].z + h[q][k].w;
        }
#pragma unroll
        for (int o = 16; o > 0; o >>= 1) sum += __shfl_xor_sync(0xffffffffu, sum, o);
        float mu = sum * (1.0f / 512.0f);
        float vs = 0.0f;
#pragma unroll
        for (int k = 0; k < 4; k++) {
            float dx;
            dx = h[q][k].x - mu; vs += dx * dx;
            dx = h[q][k].y - mu; vs += dx * dx;
            dx = h[q][k].z - mu; vs += dx * dx;
            dx = h[q][k].w - mu; vs += dx * dx;
        }
#pragma unroll
        for (int o = 16; o > 0; o >>= 1) vs += __shfl_xor_sync(0xffffffffu, vs, o);
        float var = vs * (1.0f / 512.0f);
        float sc = rsqrtf(var + 1e-5f);
#pragma unroll
        for (int k = 0; k < 4; k++) {
            float4 o4;
            o4.x = (h[q][k].x - mu) * sc * gr[k].x + br[k].x;
            o4.y = (h[q][k].y - mu) * sc * gr[k].y + br[k].y;
            o4.z = (h[q][k].z - mu) * sc * gr[k].z + br[k].z;
            o4.w = (h[q][k].w - mu) * sc * gr[k].w + br[k].w;
            int off = grow * E_DIM + lane * 4 + 128 * k;
            *(float4*)&out_pos[off] = o4;
            *(float4*)&out_neg[off] = o4;
        }
    }
}

extern "C" void kernel_launch(void* const* d_in, const int* in_sizes, int n_in,
                              void* d_out, int out_size) {
    const float* x     = (const float*)d_in[0];
    const float* W1    = (const float*)d_in[1];
    const float* b1    = (const float*)d_in[2];
    const float* coff  = (const float*)d_in[3];
    const float* W2    = (const float*)d_in[4];
    const float* b2    = (const float*)d_in[5];
    const float* gamma = (const float*)d_in[6];
    const float* beta  = (const float*)d_in[7];
    const float* g1    = (const float*)d_in[8];
    const float* g2    = (const float*)d_in[9];
    const float* wi    = (const float*)d_in[10];
    const float* ui    = (const float*)d_in[11];

    float* out = (float*)d_out;
    float* out_sampled = out;
    float* out_soft    = out + (size_t)SN * C_DIM;
    float* out_pos     = out + (size_t)2 * SN * C_DIM;
    float* out_neg     = out_pos + (size_t)SN * E_DIM;

    k_split<<<(SN + C_DIM) * E_DIM / 1024, 256>>>(x, W1);
    k_transpose<<<dim3(32, 16), dim3(32, 8)>>>(W2);

    cudaFuncSetAttribute(k1_mma, cudaFuncAttributeMaxDynamicSharedMemorySize, SMEM_K1);
    k1_mma<<<dim3(C_DIM / BN, SN / BM), 256, SMEM_K1>>>(
        b1, coff, g1, g2, wi, ui, out_sampled, out_soft);

    k1b_fix<<<FIXBLOCKS, 256>>>(x, W1, b1, coff, g1, g2, wi, ui,
                                out_sampled, out_soft);

    cudaFuncSetAttribute(k_proj_ln, cudaFuncAttributePreferredSharedMemoryCarveout, 0);
    k_proj_ln<<<SN / 64, 512>>>(b2, gamma, beta, out_pos, out_neg);
}